// round 7
// baseline (speedup 1.0000x reference)
#include <cuda_runtime.h>
#include <cuda_bf16.h>
#include <cstdint>

// ---------------------------------------------------------------------------
// CausalVAE2: B=262144, D=64, HID=256
// out layout: [x_out B*64][mu B*64][log_var B*64][y_recon B*128]
// Decoder: mma.sync bf16 3-term split; B-fragments register-resident per warp.
// ---------------------------------------------------------------------------

#define BATCH 262144
#define DD 64
#define HID 256
#define NTILES (BATCH / 128)          // 2048 row tiles of 128

// Scratch (device globals)
__device__ __align__(16) unsigned char g_abf[(size_t)NTILES * 32768]; // 64MB A' tiles [128][k hi|lo] bf16
__device__ __align__(16) unsigned char g_wbf[(size_t)DD * 65536];     // 4MB  W' per i [256][k hi|lo] bf16
__device__ int g_mask[DD * DD];

// ---- packed f32x2 helpers (encoder) ---------------------------------------
static __device__ __forceinline__ unsigned long long pk2(float lo, float hi) {
    unsigned long long r;
    asm("mov.b64 %0, {%1, %2};" : "=l"(r) : "f"(lo), "f"(hi));
    return r;
}
static __device__ __forceinline__ unsigned long long ffma2(unsigned long long a,
                                                           unsigned long long b,
                                                           unsigned long long c) {
    unsigned long long d;
    asm("fma.rn.f32x2 %0, %1, %2, %3;" : "=l"(d) : "l"(a), "l"(b), "l"(c));
    return d;
}
static __device__ __forceinline__ void upk2(unsigned long long v, float& lo, float& hi) {
    asm("mov.b64 {%0, %1}, %2;" : "=f"(lo), "=f"(hi) : "l"(v));
}

// ---- baseline tensor-core primitives --------------------------------------
static __device__ __forceinline__ uint32_t smem_u32(const void* p) {
    uint32_t a;
    asm("{ .reg .u64 t; cvta.to.shared.u64 t, %1; cvt.u32.u64 %0, t; }" : "=r"(a) : "l"(p));
    return a;
}
static __device__ __forceinline__ void ldsm_x4(uint32_t addr, uint32_t& r0, uint32_t& r1,
                                               uint32_t& r2, uint32_t& r3) {
    asm volatile("ldmatrix.sync.aligned.m8n8.x4.shared.b16 {%0,%1,%2,%3}, [%4];"
                 : "=r"(r0), "=r"(r1), "=r"(r2), "=r"(r3) : "r"(addr));
}
static __device__ __forceinline__ void mma16816(float* d, const uint32_t* a,
                                                uint32_t b0, uint32_t b1) {
    asm volatile("mma.sync.aligned.m16n8k16.row.col.f32.bf16.bf16.f32 "
                 "{%0,%1,%2,%3}, {%4,%5,%6,%7}, {%8,%9}, {%0,%1,%2,%3};"
                 : "+f"(d[0]), "+f"(d[1]), "+f"(d[2]), "+f"(d[3])
                 : "r"(a[0]), "r"(a[1]), "r"(a[2]), "r"(a[3]), "r"(b0), "r"(b1));
}
static __device__ __forceinline__ void cp_async16(uint32_t dst, const void* src) {
    asm volatile("cp.async.cg.shared.global [%0], [%1], 16;" :: "r"(dst), "l"(src));
}
#define CP_COMMIT() asm volatile("cp.async.commit_group;" ::: "memory")
#define CP_WAIT0()  asm volatile("cp.async.wait_group 0;" ::: "memory")

extern __shared__ __align__(1024) char smemraw[];

// ---------------------------------------------------------------------------
// Mask decode (robust to bool delivered as u8 / i32 / f32)
// ---------------------------------------------------------------------------
__global__ void mask_expand_kernel(const unsigned char* __restrict__ mb) {
    __shared__ int flags[2];
    __shared__ int s_mode;
    int tid = threadIdx.x;
    if (tid < 2) flags[tid] = 0;
    __syncthreads();
    for (int idx = tid; idx < DD * DD; idx += blockDim.x) {
        unsigned char b = mb[idx];
        if ((idx & 3) != 0 && b != 0) {
            atomicOr(&flags[1], 1);
            if (b > 1) atomicOr(&flags[0], 1);
        }
    }
    __syncthreads();
    if (tid == 0) s_mode = flags[0] ? 2 : (flags[1] ? 1 : 0);
    __syncthreads();
    int mode = s_mode;
    for (int idx = tid; idx < DD * DD; idx += blockDim.x) {
        int v;
        if (mode == 2)      v = (((const float*)mb)[idx] != 0.0f);
        else if (mode == 1) v = (mb[idx] != 0);
        else                v = (((const int*)mb)[idx] != 0);
        g_mask[idx] = v;
    }
}

// ---------------------------------------------------------------------------
// W-prep: per i, masked dec1_w -> bf16 hi/lo, layout [n][k-hi|k-lo].
// ---------------------------------------------------------------------------
__global__ void wprep_kernel(const float* __restrict__ w1g) {
    int i = blockIdx.x, tid = threadIdx.x;
    unsigned char* wb = g_wbf + (size_t)i * 65536;
    for (int idx = tid; idx < DD * HID; idx += blockDim.x) {
        int k = idx >> 8, n = idx & 255;
        float m = (float)g_mask[k * DD + i];
        float w = w1g[(size_t)i * DD * HID + (size_t)k * HID + n] * m;
        __nv_bfloat16 hi = __float2bfloat16(w);
        __nv_bfloat16 lo = __float2bfloat16(w - __bfloat162float(hi));
        *(__nv_bfloat16*)(wb + n * 256 + k * 2) = hi;
        *(__nv_bfloat16*)(wb + n * 256 + 128 + k * 2) = lo;
    }
}

__global__ void zero_yr_kernel(float4* __restrict__ yr) {
    size_t idx = (size_t)blockIdx.x * blockDim.x + threadIdx.x;
    size_t row = idx >> 4;
    int c4 = (int)(idx & 15);
    yr[row * 32 + 16 + c4] = make_float4(0.f, 0.f, 0.f, 0.f);
}

// ---------------------------------------------------------------------------
// Fused encoder (f32x2). Epilogue emits eps_y as A' bf16 hi/lo tiles.
// ---------------------------------------------------------------------------
__global__ __launch_bounds__(256, 1) void enc_fused_kernel(const float* __restrict__ x,
                                                           const float* __restrict__ eps,
                                                           const float* __restrict__ w1g,
                                                           const float* __restrict__ b1g,
                                                           const float* __restrict__ w2g,
                                                           const float* __restrict__ b2g,
                                                           float* __restrict__ outMu,
                                                           float* __restrict__ outLv) {
    float* smem = (float*)smemraw;
    float* sR0  = smem;                  // 32768 floats
    float* sW1  = sR0;                   // [64][256]
    float* sXT  = sR0 + DD * HID;        // [64][65]
    float* hbuf = sR0 + 32768;           // [64][256]
    float* sB1  = hbuf + DD * HID;       // 256
    float* sB2  = sB1 + HID;             // 128
    int tid = threadIdx.x;
    int row0 = blockIdx.x * 64;

    {
        const float4* w4 = (const float4*)w1g;
        float4* sW4 = (float4*)sW1;
#pragma unroll
        for (int t = 0; t < 16; t++) sW4[tid + 256 * t] = w4[tid + 256 * t];
        sB1[tid] = b1g[tid];
        if (tid < 128) sB2[tid] = b2g[tid];
        for (int idx = tid; idx < 64 * DD; idx += 256) {
            int r = idx >> 6, k = idx & 63;
            sXT[k * 65 + r] = x[(size_t)(row0 + r) * DD + k];
        }
    }
    __syncthreads();

    int cg = tid & 31, rg = tid >> 5;

    // GEMM1: h = relu(x@W1+b1)
    {
        int c0 = cg * 8, r0 = rg * 8;
        unsigned long long acc[8][4];
#pragma unroll
        for (int r = 0; r < 8; r++)
#pragma unroll
            for (int j = 0; j < 4; j++) acc[r][j] = 0ull;
        for (int k = 0; k < DD; k++) {
            float4 wa = *(const float4*)&sW1[k * HID + c0];
            float4 wb = *(const float4*)&sW1[k * HID + c0 + 4];
            unsigned long long w2[4];
            w2[0] = pk2(wa.x, wa.y); w2[1] = pk2(wa.z, wa.w);
            w2[2] = pk2(wb.x, wb.y); w2[3] = pk2(wb.z, wb.w);
#pragma unroll
            for (int r = 0; r < 8; r++) {
                float e = sXT[k * 65 + r0 + r];
                unsigned long long e2 = pk2(e, e);
#pragma unroll
                for (int j = 0; j < 4; j++) acc[r][j] = ffma2(e2, w2[j], acc[r][j]);
            }
        }
        __syncthreads();
#pragma unroll
        for (int r = 0; r < 8; r++) {
            float v[8];
#pragma unroll
            for (int j = 0; j < 4; j++) upk2(acc[r][j], v[2 * j], v[2 * j + 1]);
            float4 o1, o2;
            o1.x = fmaxf(v[0] + sB1[c0 + 0], 0.f);
            o1.y = fmaxf(v[1] + sB1[c0 + 1], 0.f);
            o1.z = fmaxf(v[2] + sB1[c0 + 2], 0.f);
            o1.w = fmaxf(v[3] + sB1[c0 + 3], 0.f);
            o2.x = fmaxf(v[4] + sB1[c0 + 4], 0.f);
            o2.y = fmaxf(v[5] + sB1[c0 + 5], 0.f);
            o2.z = fmaxf(v[6] + sB1[c0 + 6], 0.f);
            o2.w = fmaxf(v[7] + sB1[c0 + 7], 0.f);
            *(float4*)&hbuf[(r0 + r) * HID + c0] = o1;
            *(float4*)&hbuf[(r0 + r) * HID + c0 + 4] = o2;
        }
    }

    // W2 overwrite
    {
        const float4* w4 = (const float4*)w2g;
        float4* sW4 = (float4*)sR0;
#pragma unroll
        for (int t = 0; t < 32; t++) sW4[tid + 256 * t] = w4[tid + 256 * t];
    }
    __syncthreads();

    // GEMM2 + epilogue
    {
        int c0 = cg * 4, r0 = rg * 8;
        unsigned long long acc[8][2];
#pragma unroll
        for (int r = 0; r < 8; r++) { acc[r][0] = 0ull; acc[r][1] = 0ull; }
        for (int k = 0; k < HID; k++) {
            float4 wa = *(const float4*)&sR0[k * 128 + c0];
            unsigned long long w20 = pk2(wa.x, wa.y), w21 = pk2(wa.z, wa.w);
#pragma unroll
            for (int r = 0; r < 8; r++) {
                float e = hbuf[(r0 + r) * HID + k];
                unsigned long long e2 = pk2(e, e);
                acc[r][0] = ffma2(e2, w20, acc[r][0]);
                acc[r][1] = ffma2(e2, w21, acc[r][1]);
            }
        }
        __syncthreads();
        float* zb = hbuf;
#pragma unroll
        for (int r = 0; r < 8; r++) {
            float v[4];
            upk2(acc[r][0], v[0], v[1]);
            upk2(acc[r][1], v[2], v[3]);
            float4 o;
            o.x = v[0] + sB2[c0 + 0];
            o.y = v[1] + sB2[c0 + 1];
            o.z = v[2] + sB2[c0 + 2];
            o.w = v[3] + sB2[c0 + 3];
            *(float4*)&zb[(r0 + r) * 128 + c0] = o;
        }
        __syncthreads();
        for (int idx = tid; idx < 64 * 64; idx += 256) {
            int r = idx >> 6, c = idx & 63;
            int rowAbs = row0 + r;
            float mu = zb[r * 128 + c];
            float lv = zb[r * 128 + 64 + c];
            float e = eps[(size_t)rowAbs * DD + c];
            float ey = mu + expf(lv * 0.5f) * e;
            outMu[(size_t)rowAbs * DD + c] = mu;
            outLv[(size_t)rowAbs * DD + c] = lv;
            __nv_bfloat16 hi = __float2bfloat16(ey);
            __nv_bfloat16 lo = __float2bfloat16(ey - __bfloat162float(hi));
            int tile = rowAbs >> 7, rl = rowAbs & 127;
            unsigned char* tb = g_abf + (size_t)tile * 32768;
            *(__nv_bfloat16*)(tb + rl * 256 + c * 2) = hi;
            *(__nv_bfloat16*)(tb + rl * 256 + 128 + c * 2) = lo;
        }
    }
}

// ---------------------------------------------------------------------------
// Decoder v2: B-fragments register-resident.
// grid = (64 i, 128 groups of 16 tiles). 8 warps:
//   warp w: nc = w&3 (64-col chunk), rh = w>>2 (64-row half).
// smem: sB1 [0,1K), sW3 [1K,2K), psum[2][128][4] @2048 (4KB),
//       A0 @6144 (128x272=34816), A1 @40960.  W' staged once at @6144
//       (256 rows x 272B = 69632 <= A0+A1), consumed into regs, then reused.
// Total smem = 75776 B.
// ---------------------------------------------------------------------------
#define ROWPAD  272
#define SW_OFF  6144
#define SA0_OFF 6144
#define SA1_OFF 40960
#define PSUM_OFF 2048

__global__ __launch_bounds__(256, 1)
void dec_mma_kernel(const float* __restrict__ b1g,
                    const float* __restrict__ w3g,
                    const float* __restrict__ b3g,
                    float* __restrict__ outX,
                    float* __restrict__ outYr) {
    uint32_t sb = smem_u32(smemraw);
    float* sB1 = (float*)smemraw;
    float* sW3 = (float*)(smemraw + 1024);
    float* psum = (float*)(smemraw + PSUM_OFF);   // [2][128][4]
    int tid = threadIdx.x, wid = tid >> 5, lane = tid & 31;
    int i = blockIdx.x;
    int tile0 = blockIdx.y * 16;
    int nc = wid & 3, rh = wid >> 2;

    // ---- stage W' into smem (transient), plus b1/w3 ----
    // W' = 256 rows x 256 B = 4096 int4s (NOT 4352 — R6's overrun bug).
    {
        const unsigned char* src = g_wbf + (size_t)i * 65536;
        for (int idx = tid; idx < 4096; idx += 256) {
            int row = idx >> 4, c = idx & 15;
            cp_async16(sb + SW_OFF + row * ROWPAD + c * 16, src + idx * 16);
        }
        CP_COMMIT();
        sB1[tid] = b1g[i * HID + tid];
        sW3[tid] = w3g[i * HID + tid];
    }
    float b3v = b3g[i];
    CP_WAIT0();
    __syncthreads();

    // ---- load this warp's B fragments into registers (persist whole CTA) ----
    int r8 = lane & 7, g = lane >> 3;
    uint32_t Bh[4][16], Bl[4][16];
    {
        uint32_t bRow = (uint32_t)((g >> 1) * 8 + r8);
        uint32_t bCol = (uint32_t)((g & 1) * 16);
        uint32_t bBase = sb + SW_OFF + (uint32_t)(nc * 64) * ROWPAD + bRow * ROWPAD + bCol;
#pragma unroll
        for (int ks = 0; ks < 4; ks++) {
#pragma unroll
            for (int tp = 0; tp < 4; tp++) {
                uint32_t a = bBase + tp * 16 * ROWPAD + ks * 32;
                ldsm_x4(a,       Bh[ks][tp * 4], Bh[ks][tp * 4 + 1], Bh[ks][tp * 4 + 2], Bh[ks][tp * 4 + 3]);
                ldsm_x4(a + 128, Bl[ks][tp * 4], Bl[ks][tp * 4 + 1], Bl[ks][tp * 4 + 2], Bl[ks][tp * 4 + 3]);
            }
        }
    }
    __syncthreads();   // all warps done reading W' region; A buffers may reuse it

    // ---- prefetch A tile 0 ----
    {
        const unsigned char* src = g_abf + (size_t)tile0 * 32768;
        for (int idx = tid; idx < 2048; idx += 256) {
            int row = idx >> 4, c = idx & 15;
            cp_async16(sb + SA0_OFF + row * ROWPAD + c * 16, src + idx * 16);
        }
        CP_COMMIT();
    }

    // per-lane A fragment address components
    uint32_t aRowBase = (uint32_t)(rh * 64 + (g & 1) * 8 + r8);
    uint32_t aCol = (uint32_t)((g >> 1) * 16);
    int cq = (lane & 3) * 2, rq = lane >> 2;

    for (int j = 0; j < 16; j++) {
        CP_WAIT0();
        __syncthreads();
        int buf = j & 1;
        if (j + 1 < 16) {
            const unsigned char* src = g_abf + (size_t)(tile0 + j + 1) * 32768;
            uint32_t dstOff = buf ? SA0_OFF : SA1_OFF;
            for (int idx = tid; idx < 2048; idx += 256) {
                int row = idx >> 4, c = idx & 15;
                cp_async16(sb + dstOff + row * ROWPAD + c * 16, src + idx * 16);
            }
            CP_COMMIT();
        }

        uint32_t aTile = sb + (buf ? SA1_OFF : SA0_OFF);
        for (int mb = 0; mb < 4; mb++) {
            uint32_t aBase = aTile + (aRowBase + mb * 16) * ROWPAD + aCol;
            float acc[8][4];
#pragma unroll
            for (int t = 0; t < 8; t++)
#pragma unroll
                for (int q = 0; q < 4; q++) acc[t][q] = 0.f;

#pragma unroll
            for (int ks = 0; ks < 4; ks++) {
                uint32_t Ah[4], Al[4];
                ldsm_x4(aBase + ks * 32,       Ah[0], Ah[1], Ah[2], Ah[3]);
                ldsm_x4(aBase + 128 + ks * 32, Al[0], Al[1], Al[2], Al[3]);
#pragma unroll
                for (int nt = 0; nt < 8; nt++)
                    mma16816(acc[nt], Ah, Bh[ks][nt * 2], Bh[ks][nt * 2 + 1]);
#pragma unroll
                for (int nt = 0; nt < 8; nt++)
                    mma16816(acc[nt], Al, Bh[ks][nt * 2], Bh[ks][nt * 2 + 1]);
#pragma unroll
                for (int nt = 0; nt < 8; nt++)
                    mma16816(acc[nt], Ah, Bl[ks][nt * 2], Bl[ks][nt * 2 + 1]);
            }

            // fused relu + dot epilogue over this warp's 64-col chunk
            float p0 = 0.f, p1 = 0.f;
#pragma unroll
            for (int nt = 0; nt < 8; nt++) {
                int col = nc * 64 + nt * 8 + cq;
                float b1a = sB1[col], b1b = sB1[col + 1];
                float w3a = sW3[col], w3b = sW3[col + 1];
                p0 = fmaf(fmaxf(acc[nt][0] + b1a, 0.f), w3a, p0);
                p0 = fmaf(fmaxf(acc[nt][1] + b1b, 0.f), w3b, p0);
                p1 = fmaf(fmaxf(acc[nt][2] + b1a, 0.f), w3a, p1);
                p1 = fmaf(fmaxf(acc[nt][3] + b1b, 0.f), w3b, p1);
            }
#pragma unroll
            for (int off = 1; off <= 2; off <<= 1) {
                p0 += __shfl_xor_sync(0xFFFFFFFFu, p0, off);
                p1 += __shfl_xor_sync(0xFFFFFFFFu, p1, off);
            }
            if ((lane & 3) == 0) {
                int row = rh * 64 + mb * 16 + rq;
                psum[buf * 512 + row * 4 + nc] = p0;
                psum[buf * 512 + (row + 8) * 4 + nc] = p1;
            }
        }
        __syncthreads();
        if (tid < 128) {
            float o = psum[buf * 512 + tid * 4 + 0] + psum[buf * 512 + tid * 4 + 1] +
                      psum[buf * 512 + tid * 4 + 2] + psum[buf * 512 + tid * 4 + 3] + b3v;
            size_t grow = (size_t)(tile0 + j) * 128 + tid;
            outX[grow * 64 + i] = o;
            outYr[grow * 128 + i] = o;
        }
        // no extra sync needed: next iteration writes the other psum buffer
    }
}

// ---------------------------------------------------------------------------
extern "C" void kernel_launch(void* const* d_in, const int* in_sizes, int n_in,
                              void* d_out, int out_size) {
    const float* x      = (const float*)d_in[0];
    const float* eps    = (const float*)d_in[1];
    const float* enc1_w = (const float*)d_in[2];
    const float* enc1_b = (const float*)d_in[3];
    const float* enc3_w = (const float*)d_in[4];
    const float* enc3_b = (const float*)d_in[5];
    const float* dec1_w = (const float*)d_in[6];
    const float* dec1_b = (const float*)d_in[7];
    const float* dec3_w = (const float*)d_in[8];
    const float* dec3_b = (const float*)d_in[9];
    const unsigned char* bmask = (const unsigned char*)d_in[10];
    (void)n_in; (void)in_sizes; (void)out_size;

    float* out   = (float*)d_out;
    float* outX  = out;
    float* outMu = out + (size_t)BATCH * DD;
    float* outLv = out + (size_t)2 * BATCH * DD;
    float* outYr = out + (size_t)3 * BATCH * DD;

    size_t sEnc = (size_t)(32768 + DD * HID + HID + 128) * sizeof(float);  // 198,144
    size_t sDec = 75776;
    cudaFuncSetAttribute(enc_fused_kernel, cudaFuncAttributeMaxDynamicSharedMemorySize, (int)sEnc);
    cudaFuncSetAttribute(dec_mma_kernel,   cudaFuncAttributeMaxDynamicSharedMemorySize, (int)sDec);

    mask_expand_kernel<<<1, 256>>>(bmask);
    wprep_kernel<<<DD, 256>>>(dec1_w);
    zero_yr_kernel<<<(BATCH * 16) / 256, 256>>>((float4*)outYr);
    enc_fused_kernel<<<BATCH / 64, 256, sEnc>>>(x, eps, enc1_w, enc1_b,
                                                enc3_w, enc3_b, outMu, outLv);
    dec_mma_kernel<<<dim3(DD, 128), 256, sDec>>>(dec1_b, dec3_w, dec3_b, outX, outYr);
}

// round 8
// speedup vs baseline: 1.1999x; 1.1999x over previous
#include <cuda_runtime.h>
#include <cuda_bf16.h>
#include <cstdint>

// ---------------------------------------------------------------------------
// CausalVAE2: B=262144, D=64, HID=256
// out layout: [x_out B*64][mu B*64][log_var B*64][y_recon B*128]
// Decoder: mma.sync bf16 3-term split, register-resident B fragments,
// K truncated per i (mask[k][i]=0 for k>i by DAG construction).
// ---------------------------------------------------------------------------

#define BATCH 262144
#define DD 64
#define HID 256
#define NTILES (BATCH / 128)          // 2048 row tiles of 128

// Scratch (device globals)
__device__ __align__(16) unsigned char g_abf[(size_t)NTILES * 32768]; // 64MB A' tiles [128][k hi|lo] bf16
__device__ __align__(16) unsigned char g_wbf[(size_t)DD * 65536];     // 4MB  W' per i [256][k hi|lo] bf16
__device__ int g_mask[DD * DD];

// ---- packed f32x2 helpers (encoder) ---------------------------------------
static __device__ __forceinline__ unsigned long long pk2(float lo, float hi) {
    unsigned long long r;
    asm("mov.b64 %0, {%1, %2};" : "=l"(r) : "f"(lo), "f"(hi));
    return r;
}
static __device__ __forceinline__ unsigned long long ffma2(unsigned long long a,
                                                           unsigned long long b,
                                                           unsigned long long c) {
    unsigned long long d;
    asm("fma.rn.f32x2 %0, %1, %2, %3;" : "=l"(d) : "l"(a), "l"(b), "l"(c));
    return d;
}
static __device__ __forceinline__ void upk2(unsigned long long v, float& lo, float& hi) {
    asm("mov.b64 {%0, %1}, %2;" : "=f"(lo), "=f"(hi) : "l"(v));
}

// ---- baseline tensor-core primitives --------------------------------------
static __device__ __forceinline__ uint32_t smem_u32(const void* p) {
    uint32_t a;
    asm("{ .reg .u64 t; cvta.to.shared.u64 t, %1; cvt.u32.u64 %0, t; }" : "=r"(a) : "l"(p));
    return a;
}
static __device__ __forceinline__ void ldsm_x4(uint32_t addr, uint32_t& r0, uint32_t& r1,
                                               uint32_t& r2, uint32_t& r3) {
    asm volatile("ldmatrix.sync.aligned.m8n8.x4.shared.b16 {%0,%1,%2,%3}, [%4];"
                 : "=r"(r0), "=r"(r1), "=r"(r2), "=r"(r3) : "r"(addr));
}
static __device__ __forceinline__ void mma16816(float* d, const uint32_t* a,
                                                uint32_t b0, uint32_t b1) {
    asm volatile("mma.sync.aligned.m16n8k16.row.col.f32.bf16.bf16.f32 "
                 "{%0,%1,%2,%3}, {%4,%5,%6,%7}, {%8,%9}, {%0,%1,%2,%3};"
                 : "+f"(d[0]), "+f"(d[1]), "+f"(d[2]), "+f"(d[3])
                 : "r"(a[0]), "r"(a[1]), "r"(a[2]), "r"(a[3]), "r"(b0), "r"(b1));
}
static __device__ __forceinline__ void cp_async16(uint32_t dst, const void* src) {
    asm volatile("cp.async.cg.shared.global [%0], [%1], 16;" :: "r"(dst), "l"(src));
}
#define CP_COMMIT() asm volatile("cp.async.commit_group;" ::: "memory")
#define CP_WAIT0()  asm volatile("cp.async.wait_group 0;" ::: "memory")

extern __shared__ __align__(1024) char smemraw[];

// ---------------------------------------------------------------------------
// Mask decode (robust to bool delivered as u8 / i32 / f32)
// ---------------------------------------------------------------------------
__global__ void mask_expand_kernel(const unsigned char* __restrict__ mb) {
    __shared__ int flags[2];
    __shared__ int s_mode;
    int tid = threadIdx.x;
    if (tid < 2) flags[tid] = 0;
    __syncthreads();
    for (int idx = tid; idx < DD * DD; idx += blockDim.x) {
        unsigned char b = mb[idx];
        if ((idx & 3) != 0 && b != 0) {
            atomicOr(&flags[1], 1);
            if (b > 1) atomicOr(&flags[0], 1);
        }
    }
    __syncthreads();
    if (tid == 0) s_mode = flags[0] ? 2 : (flags[1] ? 1 : 0);
    __syncthreads();
    int mode = s_mode;
    for (int idx = tid; idx < DD * DD; idx += blockDim.x) {
        int v;
        if (mode == 2)      v = (((const float*)mb)[idx] != 0.0f);
        else if (mode == 1) v = (mb[idx] != 0);
        else                v = (((const int*)mb)[idx] != 0);
        g_mask[idx] = v;
    }
}

// ---------------------------------------------------------------------------
// W-prep: per i, masked dec1_w -> bf16 hi/lo, layout [n][k-hi|k-lo].
// ---------------------------------------------------------------------------
__global__ void wprep_kernel(const float* __restrict__ w1g) {
    int i = blockIdx.x, tid = threadIdx.x;
    unsigned char* wb = g_wbf + (size_t)i * 65536;
    for (int idx = tid; idx < DD * HID; idx += blockDim.x) {
        int k = idx >> 8, n = idx & 255;
        float m = (float)g_mask[k * DD + i];
        float w = w1g[(size_t)i * DD * HID + (size_t)k * HID + n] * m;
        __nv_bfloat16 hi = __float2bfloat16(w);
        __nv_bfloat16 lo = __float2bfloat16(w - __bfloat162float(hi));
        *(__nv_bfloat16*)(wb + n * 256 + k * 2) = hi;
        *(__nv_bfloat16*)(wb + n * 256 + 128 + k * 2) = lo;
    }
}

__global__ void zero_yr_kernel(float4* __restrict__ yr) {
    size_t idx = (size_t)blockIdx.x * blockDim.x + threadIdx.x;
    size_t row = idx >> 4;
    int c4 = (int)(idx & 15);
    yr[row * 32 + 16 + c4] = make_float4(0.f, 0.f, 0.f, 0.f);
}

// ---------------------------------------------------------------------------
// Fused encoder (f32x2). Epilogue emits eps_y as A' bf16 hi/lo tiles.
// ---------------------------------------------------------------------------
__global__ __launch_bounds__(256, 1) void enc_fused_kernel(const float* __restrict__ x,
                                                           const float* __restrict__ eps,
                                                           const float* __restrict__ w1g,
                                                           const float* __restrict__ b1g,
                                                           const float* __restrict__ w2g,
                                                           const float* __restrict__ b2g,
                                                           float* __restrict__ outMu,
                                                           float* __restrict__ outLv) {
    float* smem = (float*)smemraw;
    float* sR0  = smem;                  // 32768 floats
    float* sW1  = sR0;                   // [64][256]
    float* sXT  = sR0 + DD * HID;        // [64][65]
    float* hbuf = sR0 + 32768;           // [64][256]
    float* sB1  = hbuf + DD * HID;       // 256
    float* sB2  = sB1 + HID;             // 128
    int tid = threadIdx.x;
    int row0 = blockIdx.x * 64;

    {
        const float4* w4 = (const float4*)w1g;
        float4* sW4 = (float4*)sW1;
#pragma unroll
        for (int t = 0; t < 16; t++) sW4[tid + 256 * t] = w4[tid + 256 * t];
        sB1[tid] = b1g[tid];
        if (tid < 128) sB2[tid] = b2g[tid];
        for (int idx = tid; idx < 64 * DD; idx += 256) {
            int r = idx >> 6, k = idx & 63;
            sXT[k * 65 + r] = x[(size_t)(row0 + r) * DD + k];
        }
    }
    __syncthreads();

    int cg = tid & 31, rg = tid >> 5;

    // GEMM1: h = relu(x@W1+b1)
    {
        int c0 = cg * 8, r0 = rg * 8;
        unsigned long long acc[8][4];
#pragma unroll
        for (int r = 0; r < 8; r++)
#pragma unroll
            for (int j = 0; j < 4; j++) acc[r][j] = 0ull;
        for (int k = 0; k < DD; k++) {
            float4 wa = *(const float4*)&sW1[k * HID + c0];
            float4 wb = *(const float4*)&sW1[k * HID + c0 + 4];
            unsigned long long w2[4];
            w2[0] = pk2(wa.x, wa.y); w2[1] = pk2(wa.z, wa.w);
            w2[2] = pk2(wb.x, wb.y); w2[3] = pk2(wb.z, wb.w);
#pragma unroll
            for (int r = 0; r < 8; r++) {
                float e = sXT[k * 65 + r0 + r];
                unsigned long long e2 = pk2(e, e);
#pragma unroll
                for (int j = 0; j < 4; j++) acc[r][j] = ffma2(e2, w2[j], acc[r][j]);
            }
        }
        __syncthreads();
#pragma unroll
        for (int r = 0; r < 8; r++) {
            float v[8];
#pragma unroll
            for (int j = 0; j < 4; j++) upk2(acc[r][j], v[2 * j], v[2 * j + 1]);
            float4 o1, o2;
            o1.x = fmaxf(v[0] + sB1[c0 + 0], 0.f);
            o1.y = fmaxf(v[1] + sB1[c0 + 1], 0.f);
            o1.z = fmaxf(v[2] + sB1[c0 + 2], 0.f);
            o1.w = fmaxf(v[3] + sB1[c0 + 3], 0.f);
            o2.x = fmaxf(v[4] + sB1[c0 + 4], 0.f);
            o2.y = fmaxf(v[5] + sB1[c0 + 5], 0.f);
            o2.z = fmaxf(v[6] + sB1[c0 + 6], 0.f);
            o2.w = fmaxf(v[7] + sB1[c0 + 7], 0.f);
            *(float4*)&hbuf[(r0 + r) * HID + c0] = o1;
            *(float4*)&hbuf[(r0 + r) * HID + c0 + 4] = o2;
        }
    }

    // W2 overwrite
    {
        const float4* w4 = (const float4*)w2g;
        float4* sW4 = (float4*)sR0;
#pragma unroll
        for (int t = 0; t < 32; t++) sW4[tid + 256 * t] = w4[tid + 256 * t];
    }
    __syncthreads();

    // GEMM2 + epilogue
    {
        int c0 = cg * 4, r0 = rg * 8;
        unsigned long long acc[8][2];
#pragma unroll
        for (int r = 0; r < 8; r++) { acc[r][0] = 0ull; acc[r][1] = 0ull; }
        for (int k = 0; k < HID; k++) {
            float4 wa = *(const float4*)&sR0[k * 128 + c0];
            unsigned long long w20 = pk2(wa.x, wa.y), w21 = pk2(wa.z, wa.w);
#pragma unroll
            for (int r = 0; r < 8; r++) {
                float e = hbuf[(r0 + r) * HID + k];
                unsigned long long e2 = pk2(e, e);
                acc[r][0] = ffma2(e2, w20, acc[r][0]);
                acc[r][1] = ffma2(e2, w21, acc[r][1]);
            }
        }
        __syncthreads();
        float* zb = hbuf;
#pragma unroll
        for (int r = 0; r < 8; r++) {
            float v[4];
            upk2(acc[r][0], v[0], v[1]);
            upk2(acc[r][1], v[2], v[3]);
            float4 o;
            o.x = v[0] + sB2[c0 + 0];
            o.y = v[1] + sB2[c0 + 1];
            o.z = v[2] + sB2[c0 + 2];
            o.w = v[3] + sB2[c0 + 3];
            *(float4*)&zb[(r0 + r) * 128 + c0] = o;
        }
        __syncthreads();
        for (int idx = tid; idx < 64 * 64; idx += 256) {
            int r = idx >> 6, c = idx & 63;
            int rowAbs = row0 + r;
            float mu = zb[r * 128 + c];
            float lv = zb[r * 128 + 64 + c];
            float e = eps[(size_t)rowAbs * DD + c];
            float ey = mu + expf(lv * 0.5f) * e;
            outMu[(size_t)rowAbs * DD + c] = mu;
            outLv[(size_t)rowAbs * DD + c] = lv;
            __nv_bfloat16 hi = __float2bfloat16(ey);
            __nv_bfloat16 lo = __float2bfloat16(ey - __bfloat162float(hi));
            int tile = rowAbs >> 7, rl = rowAbs & 127;
            unsigned char* tb = g_abf + (size_t)tile * 32768;
            *(__nv_bfloat16*)(tb + rl * 256 + c * 2) = hi;
            *(__nv_bfloat16*)(tb + rl * 256 + 128 + c * 2) = lo;
        }
    }
}

// ---------------------------------------------------------------------------
// Decoder v3: register-resident B + triangular-K truncation.
// kmax = i/16 + 1 k-steps of 16 (mask[k][i] == 0 for k > i by construction).
// grid = (64 i, 128 groups of 16 tiles). 8 warps:
//   warp w: nc = w&3 (64-col chunk), rh = w>>2 (64-row half).
// smem: sB1 [0,1K), sW3 [1K,2K), psum[2][128][4] @2048 (4KB),
//       A0 @6144 (128x272=34816), A1 @40960. W' staged once at @6144.
// Total smem = 75776 B.
// ---------------------------------------------------------------------------
#define ROWPAD  272
#define SW_OFF  6144
#define SA0_OFF 6144
#define SA1_OFF 40960
#define PSUM_OFF 2048

__global__ __launch_bounds__(256, 1)
void dec_mma_kernel(const float* __restrict__ b1g,
                    const float* __restrict__ w3g,
                    const float* __restrict__ b3g,
                    float* __restrict__ outX,
                    float* __restrict__ outYr) {
    uint32_t sb = smem_u32(smemraw);
    float* sB1 = (float*)smemraw;
    float* sW3 = (float*)(smemraw + 1024);
    float* psum = (float*)(smemraw + PSUM_OFF);   // [2][128][4]
    int tid = threadIdx.x, wid = tid >> 5, lane = tid & 31;
    int i = blockIdx.x;
    int tile0 = blockIdx.y * 16;
    int nc = wid & 3, rh = wid >> 2;
    const int kmax = (i >> 4) + 1;                // 1..4 k-steps of 16

    // ---- stage W' (only rows' first kmax*16 k hi + lo halves needed; but W'
    //      is just 64KB once per CTA — stage only needed chunks) ----
    {
        const unsigned char* src = g_wbf + (size_t)i * 65536;
        int row = tid >> 1, half = tid & 1;       // 2 threads per row, 256 rows -> rows 0..127
        // rows 0..127 and 128..255 handled by two passes
#pragma unroll
        for (int pass = 0; pass < 2; pass++) {
            int r = row + pass * 128;
#pragma unroll
            for (int cc = 0; cc < 8; cc++) {      // cc strided by 2 via half
                int c = cc * 2 + half;
                if (c < 2 * kmax) {               // hi chunk
                    cp_async16(sb + SW_OFF + r * ROWPAD + c * 16, src + r * 256 + c * 16);
                    cp_async16(sb + SW_OFF + r * ROWPAD + (c + 8) * 16, src + r * 256 + (c + 8) * 16);
                }
            }
        }
        CP_COMMIT();
        sB1[tid] = b1g[i * HID + tid];
        sW3[tid] = w3g[i * HID + tid];
    }
    float b3v = b3g[i];
    CP_WAIT0();
    __syncthreads();

    // ---- load this warp's B fragments into registers (persist whole CTA) ----
    int r8 = lane & 7, g = lane >> 3;
    uint32_t Bh[4][16], Bl[4][16];
#pragma unroll
    for (int ks = 0; ks < 4; ks++)
#pragma unroll
        for (int q = 0; q < 16; q++) { Bh[ks][q] = 0u; Bl[ks][q] = 0u; }
    {
        uint32_t bRow = (uint32_t)((g >> 1) * 8 + r8);
        uint32_t bCol = (uint32_t)((g & 1) * 16);
        uint32_t bBase = sb + SW_OFF + (uint32_t)(nc * 64) * ROWPAD + bRow * ROWPAD + bCol;
#pragma unroll
        for (int ks = 0; ks < 4; ks++) {
            if (ks < kmax) {
#pragma unroll
                for (int tp = 0; tp < 4; tp++) {
                    uint32_t a = bBase + tp * 16 * ROWPAD + ks * 32;
                    ldsm_x4(a,       Bh[ks][tp * 4], Bh[ks][tp * 4 + 1], Bh[ks][tp * 4 + 2], Bh[ks][tp * 4 + 3]);
                    ldsm_x4(a + 128, Bl[ks][tp * 4], Bl[ks][tp * 4 + 1], Bl[ks][tp * 4 + 2], Bl[ks][tp * 4 + 3]);
                }
            }
        }
    }
    __syncthreads();   // all warps done reading W' region; A buffers may reuse it

    // ---- prefetch A tile 0 (truncated: only k < kmax*16, hi+lo) ----
    {
        const unsigned char* src = g_abf + (size_t)tile0 * 32768;
        int row = tid >> 1, half = tid & 1;
#pragma unroll
        for (int cc = 0; cc < 8; cc++) {
            int c = cc * 2 + half;
            if (c < 2 * kmax) {
                cp_async16(sb + SA0_OFF + row * ROWPAD + c * 16, src + row * 256 + c * 16);
                cp_async16(sb + SA0_OFF + row * ROWPAD + (c + 8) * 16, src + row * 256 + (c + 8) * 16);
            }
        }
        CP_COMMIT();
    }

    // per-lane A fragment address components
    uint32_t aRowBase = (uint32_t)(rh * 64 + (g & 1) * 8 + r8);
    uint32_t aCol = (uint32_t)((g >> 1) * 16);
    int cq = (lane & 3) * 2, rq = lane >> 2;
    int rowh = tid >> 1, halfh = tid & 1;

    for (int j = 0; j < 16; j++) {
        CP_WAIT0();
        __syncthreads();
        int buf = j & 1;
        if (j + 1 < 16) {
            const unsigned char* src = g_abf + (size_t)(tile0 + j + 1) * 32768;
            uint32_t dstOff = buf ? SA0_OFF : SA1_OFF;
#pragma unroll
            for (int cc = 0; cc < 8; cc++) {
                int c = cc * 2 + halfh;
                if (c < 2 * kmax) {
                    cp_async16(sb + dstOff + rowh * ROWPAD + c * 16, src + rowh * 256 + c * 16);
                    cp_async16(sb + dstOff + rowh * ROWPAD + (c + 8) * 16, src + rowh * 256 + (c + 8) * 16);
                }
            }
            CP_COMMIT();
        }

        uint32_t aTile = sb + (buf ? SA1_OFF : SA0_OFF);
        for (int mb = 0; mb < 4; mb++) {
            uint32_t aBase = aTile + (aRowBase + mb * 16) * ROWPAD + aCol;
            float acc[8][4];
#pragma unroll
            for (int t = 0; t < 8; t++)
#pragma unroll
                for (int q = 0; q < 4; q++) acc[t][q] = 0.f;

#pragma unroll
            for (int ks = 0; ks < 4; ks++) {
                if (ks < kmax) {
                    uint32_t Ah[4], Al[4];
                    ldsm_x4(aBase + ks * 32,       Ah[0], Ah[1], Ah[2], Ah[3]);
                    ldsm_x4(aBase + 128 + ks * 32, Al[0], Al[1], Al[2], Al[3]);
#pragma unroll
                    for (int nt = 0; nt < 8; nt++)
                        mma16816(acc[nt], Ah, Bh[ks][nt * 2], Bh[ks][nt * 2 + 1]);
#pragma unroll
                    for (int nt = 0; nt < 8; nt++)
                        mma16816(acc[nt], Al, Bh[ks][nt * 2], Bh[ks][nt * 2 + 1]);
#pragma unroll
                    for (int nt = 0; nt < 8; nt++)
                        mma16816(acc[nt], Ah, Bl[ks][nt * 2], Bl[ks][nt * 2 + 1]);
                }
            }

            // fused relu + dot epilogue over this warp's 64-col chunk
            float p0 = 0.f, p1 = 0.f;
#pragma unroll
            for (int nt = 0; nt < 8; nt++) {
                int col = nc * 64 + nt * 8 + cq;
                float b1a = sB1[col], b1b = sB1[col + 1];
                float w3a = sW3[col], w3b = sW3[col + 1];
                p0 = fmaf(fmaxf(acc[nt][0] + b1a, 0.f), w3a, p0);
                p0 = fmaf(fmaxf(acc[nt][1] + b1b, 0.f), w3b, p0);
                p1 = fmaf(fmaxf(acc[nt][2] + b1a, 0.f), w3a, p1);
                p1 = fmaf(fmaxf(acc[nt][3] + b1b, 0.f), w3b, p1);
            }
#pragma unroll
            for (int off = 1; off <= 2; off <<= 1) {
                p0 += __shfl_xor_sync(0xFFFFFFFFu, p0, off);
                p1 += __shfl_xor_sync(0xFFFFFFFFu, p1, off);
            }
            if ((lane & 3) == 0) {
                int row = rh * 64 + mb * 16 + rq;
                psum[buf * 512 + row * 4 + nc] = p0;
                psum[buf * 512 + (row + 8) * 4 + nc] = p1;
            }
        }
        __syncthreads();
        if (tid < 128) {
            float o = psum[buf * 512 + tid * 4 + 0] + psum[buf * 512 + tid * 4 + 1] +
                      psum[buf * 512 + tid * 4 + 2] + psum[buf * 512 + tid * 4 + 3] + b3v;
            size_t grow = (size_t)(tile0 + j) * 128 + tid;
            outX[grow * 64 + i] = o;
            outYr[grow * 128 + i] = o;
        }
        // no extra sync needed: next iteration writes the other psum buffer
    }
}

// ---------------------------------------------------------------------------
extern "C" void kernel_launch(void* const* d_in, const int* in_sizes, int n_in,
                              void* d_out, int out_size) {
    const float* x      = (const float*)d_in[0];
    const float* eps    = (const float*)d_in[1];
    const float* enc1_w = (const float*)d_in[2];
    const float* enc1_b = (const float*)d_in[3];
    const float* enc3_w = (const float*)d_in[4];
    const float* enc3_b = (const float*)d_in[5];
    const float* dec1_w = (const float*)d_in[6];
    const float* dec1_b = (const float*)d_in[7];
    const float* dec3_w = (const float*)d_in[8];
    const float* dec3_b = (const float*)d_in[9];
    const unsigned char* bmask = (const unsigned char*)d_in[10];
    (void)n_in; (void)in_sizes; (void)out_size;

    float* out   = (float*)d_out;
    float* outX  = out;
    float* outMu = out + (size_t)BATCH * DD;
    float* outLv = out + (size_t)2 * BATCH * DD;
    float* outYr = out + (size_t)3 * BATCH * DD;

    size_t sEnc = (size_t)(32768 + DD * HID + HID + 128) * sizeof(float);  // 198,144
    size_t sDec = 75776;
    cudaFuncSetAttribute(enc_fused_kernel, cudaFuncAttributeMaxDynamicSharedMemorySize, (int)sEnc);
    cudaFuncSetAttribute(dec_mma_kernel,   cudaFuncAttributeMaxDynamicSharedMemorySize, (int)sDec);

    mask_expand_kernel<<<1, 256>>>(bmask);
    wprep_kernel<<<DD, 256>>>(dec1_w);
    zero_yr_kernel<<<(BATCH * 16) / 256, 256>>>((float4*)outYr);
    enc_fused_kernel<<<BATCH / 64, 256, sEnc>>>(x, eps, enc1_w, enc1_b,
                                                enc3_w, enc3_b, outMu, outLv);
    dec_mma_kernel<<<dim3(DD, 128), 256, sDec>>>(dec1_b, dec3_w, dec3_b, outX, outYr);
}

// round 9
// speedup vs baseline: 1.3657x; 1.1382x over previous
#include <cuda_runtime.h>
#include <cuda_fp16.h>
#include <cstdint>

// ---------------------------------------------------------------------------
// CausalVAE2: B=262144, D=64, HID=256
// out layout: [x_out B*64][mu B*64][log_var B*64][y_recon B*128]
// Decoder: mma.sync fp16 2-term split (A=Ahi+Alo fp16, W=fp16), register-
// resident B fragments, triangular-K truncation, M=256 row tiles.
// ---------------------------------------------------------------------------

#define BATCH 262144
#define DD 64
#define HID 256
#define NT256 (BATCH / 256)           // 1024 row tiles of 256

// Scratch (device globals)
// A': flat [row][k 0..63 hi fp16 (128B) | k 0..63 lo fp16 (128B)]
__device__ __align__(16) unsigned char g_abf[(size_t)BATCH * 256];  // 64MB
// W' per i: [n 0..255][k hi fp16 128B]
__device__ __align__(16) unsigned char g_wbf[(size_t)DD * 32768];   // 2MB
__device__ int g_mask[DD * DD];

// ---- packed f32x2 helpers (encoder) ---------------------------------------
static __device__ __forceinline__ unsigned long long pk2(float lo, float hi) {
    unsigned long long r;
    asm("mov.b64 %0, {%1, %2};" : "=l"(r) : "f"(lo), "f"(hi));
    return r;
}
static __device__ __forceinline__ unsigned long long ffma2(unsigned long long a,
                                                           unsigned long long b,
                                                           unsigned long long c) {
    unsigned long long d;
    asm("fma.rn.f32x2 %0, %1, %2, %3;" : "=l"(d) : "l"(a), "l"(b), "l"(c));
    return d;
}
static __device__ __forceinline__ void upk2(unsigned long long v, float& lo, float& hi) {
    asm("mov.b64 {%0, %1}, %2;" : "=f"(lo), "=f"(hi) : "l"(v));
}

// ---- baseline tensor-core primitives --------------------------------------
static __device__ __forceinline__ uint32_t smem_u32(const void* p) {
    uint32_t a;
    asm("{ .reg .u64 t; cvta.to.shared.u64 t, %1; cvt.u32.u64 %0, t; }" : "=r"(a) : "l"(p));
    return a;
}
static __device__ __forceinline__ void ldsm_x4(uint32_t addr, uint32_t& r0, uint32_t& r1,
                                               uint32_t& r2, uint32_t& r3) {
    asm volatile("ldmatrix.sync.aligned.m8n8.x4.shared.b16 {%0,%1,%2,%3}, [%4];"
                 : "=r"(r0), "=r"(r1), "=r"(r2), "=r"(r3) : "r"(addr));
}
static __device__ __forceinline__ void mma16816(float* d, const uint32_t* a,
                                                uint32_t b0, uint32_t b1) {
    asm volatile("mma.sync.aligned.m16n8k16.row.col.f32.f16.f16.f32 "
                 "{%0,%1,%2,%3}, {%4,%5,%6,%7}, {%8,%9}, {%0,%1,%2,%3};"
                 : "+f"(d[0]), "+f"(d[1]), "+f"(d[2]), "+f"(d[3])
                 : "r"(a[0]), "r"(a[1]), "r"(a[2]), "r"(a[3]), "r"(b0), "r"(b1));
}
static __device__ __forceinline__ void cp_async16(uint32_t dst, const void* src) {
    asm volatile("cp.async.cg.shared.global [%0], [%1], 16;" :: "r"(dst), "l"(src));
}
#define CP_COMMIT() asm volatile("cp.async.commit_group;" ::: "memory")
#define CP_WAIT0()  asm volatile("cp.async.wait_group 0;" ::: "memory")

extern __shared__ __align__(1024) char smemraw[];

// ---------------------------------------------------------------------------
// Mask decode (robust to bool delivered as u8 / i32 / f32)
// ---------------------------------------------------------------------------
__global__ void mask_expand_kernel(const unsigned char* __restrict__ mb) {
    __shared__ int flags[2];
    __shared__ int s_mode;
    int tid = threadIdx.x;
    if (tid < 2) flags[tid] = 0;
    __syncthreads();
    for (int idx = tid; idx < DD * DD; idx += blockDim.x) {
        unsigned char b = mb[idx];
        if ((idx & 3) != 0 && b != 0) {
            atomicOr(&flags[1], 1);
            if (b > 1) atomicOr(&flags[0], 1);
        }
    }
    __syncthreads();
    if (tid == 0) s_mode = flags[0] ? 2 : (flags[1] ? 1 : 0);
    __syncthreads();
    int mode = s_mode;
    for (int idx = tid; idx < DD * DD; idx += blockDim.x) {
        int v;
        if (mode == 2)      v = (((const float*)mb)[idx] != 0.0f);
        else if (mode == 1) v = (mb[idx] != 0);
        else                v = (((const int*)mb)[idx] != 0);
        g_mask[idx] = v;
    }
}

// ---------------------------------------------------------------------------
// W-prep: per i, masked dec1_w -> fp16, layout [n][k 0..63].
// ---------------------------------------------------------------------------
__global__ void wprep_kernel(const float* __restrict__ w1g) {
    int i = blockIdx.x, tid = threadIdx.x;
    unsigned char* wb = g_wbf + (size_t)i * 32768;
    for (int idx = tid; idx < DD * HID; idx += blockDim.x) {
        int k = idx >> 8, n = idx & 255;
        float m = (float)g_mask[k * DD + i];
        float w = w1g[(size_t)i * DD * HID + (size_t)k * HID + n] * m;
        *(__half*)(wb + n * 128 + k * 2) = __float2half_rn(w);
    }
}

__global__ void zero_yr_kernel(float4* __restrict__ yr) {
    size_t idx = (size_t)blockIdx.x * blockDim.x + threadIdx.x;
    size_t row = idx >> 4;
    int c4 = (int)(idx & 15);
    yr[row * 32 + 16 + c4] = make_float4(0.f, 0.f, 0.f, 0.f);
}

// ---------------------------------------------------------------------------
// Fused encoder (f32x2). Epilogue emits eps_y as fp16 hi/lo rows in g_abf.
// ---------------------------------------------------------------------------
__global__ __launch_bounds__(256, 1) void enc_fused_kernel(const float* __restrict__ x,
                                                           const float* __restrict__ eps,
                                                           const float* __restrict__ w1g,
                                                           const float* __restrict__ b1g,
                                                           const float* __restrict__ w2g,
                                                           const float* __restrict__ b2g,
                                                           float* __restrict__ outMu,
                                                           float* __restrict__ outLv) {
    float* smem = (float*)smemraw;
    float* sR0  = smem;                  // 32768 floats
    float* sW1  = sR0;                   // [64][256]
    float* sXT  = sR0 + DD * HID;        // [64][65]
    float* hbuf = sR0 + 32768;           // [64][256]
    float* sB1  = hbuf + DD * HID;       // 256
    float* sB2  = sB1 + HID;             // 128
    int tid = threadIdx.x;
    int row0 = blockIdx.x * 64;

    {
        const float4* w4 = (const float4*)w1g;
        float4* sW4 = (float4*)sW1;
#pragma unroll
        for (int t = 0; t < 16; t++) sW4[tid + 256 * t] = w4[tid + 256 * t];
        sB1[tid] = b1g[tid];
        if (tid < 128) sB2[tid] = b2g[tid];
        for (int idx = tid; idx < 64 * DD; idx += 256) {
            int r = idx >> 6, k = idx & 63;
            sXT[k * 65 + r] = x[(size_t)(row0 + r) * DD + k];
        }
    }
    __syncthreads();

    int cg = tid & 31, rg = tid >> 5;

    // GEMM1: h = relu(x@W1+b1)
    {
        int c0 = cg * 8, r0 = rg * 8;
        unsigned long long acc[8][4];
#pragma unroll
        for (int r = 0; r < 8; r++)
#pragma unroll
            for (int j = 0; j < 4; j++) acc[r][j] = 0ull;
        for (int k = 0; k < DD; k++) {
            float4 wa = *(const float4*)&sW1[k * HID + c0];
            float4 wb = *(const float4*)&sW1[k * HID + c0 + 4];
            unsigned long long w2[4];
            w2[0] = pk2(wa.x, wa.y); w2[1] = pk2(wa.z, wa.w);
            w2[2] = pk2(wb.x, wb.y); w2[3] = pk2(wb.z, wb.w);
#pragma unroll
            for (int r = 0; r < 8; r++) {
                float e = sXT[k * 65 + r0 + r];
                unsigned long long e2 = pk2(e, e);
#pragma unroll
                for (int j = 0; j < 4; j++) acc[r][j] = ffma2(e2, w2[j], acc[r][j]);
            }
        }
        __syncthreads();
#pragma unroll
        for (int r = 0; r < 8; r++) {
            float v[8];
#pragma unroll
            for (int j = 0; j < 4; j++) upk2(acc[r][j], v[2 * j], v[2 * j + 1]);
            float4 o1, o2;
            o1.x = fmaxf(v[0] + sB1[c0 + 0], 0.f);
            o1.y = fmaxf(v[1] + sB1[c0 + 1], 0.f);
            o1.z = fmaxf(v[2] + sB1[c0 + 2], 0.f);
            o1.w = fmaxf(v[3] + sB1[c0 + 3], 0.f);
            o2.x = fmaxf(v[4] + sB1[c0 + 4], 0.f);
            o2.y = fmaxf(v[5] + sB1[c0 + 5], 0.f);
            o2.z = fmaxf(v[6] + sB1[c0 + 6], 0.f);
            o2.w = fmaxf(v[7] + sB1[c0 + 7], 0.f);
            *(float4*)&hbuf[(r0 + r) * HID + c0] = o1;
            *(float4*)&hbuf[(r0 + r) * HID + c0 + 4] = o2;
        }
    }

    // W2 overwrite
    {
        const float4* w4 = (const float4*)w2g;
        float4* sW4 = (float4*)sR0;
#pragma unroll
        for (int t = 0; t < 32; t++) sW4[tid + 256 * t] = w4[tid + 256 * t];
    }
    __syncthreads();

    // GEMM2 + epilogue
    {
        int c0 = cg * 4, r0 = rg * 8;
        unsigned long long acc[8][2];
#pragma unroll
        for (int r = 0; r < 8; r++) { acc[r][0] = 0ull; acc[r][1] = 0ull; }
        for (int k = 0; k < HID; k++) {
            float4 wa = *(const float4*)&sR0[k * 128 + c0];
            unsigned long long w20 = pk2(wa.x, wa.y), w21 = pk2(wa.z, wa.w);
#pragma unroll
            for (int r = 0; r < 8; r++) {
                float e = hbuf[(r0 + r) * HID + k];
                unsigned long long e2 = pk2(e, e);
                acc[r][0] = ffma2(e2, w20, acc[r][0]);
                acc[r][1] = ffma2(e2, w21, acc[r][1]);
            }
        }
        __syncthreads();
        float* zb = hbuf;
#pragma unroll
        for (int r = 0; r < 8; r++) {
            float v[4];
            upk2(acc[r][0], v[0], v[1]);
            upk2(acc[r][1], v[2], v[3]);
            float4 o;
            o.x = v[0] + sB2[c0 + 0];
            o.y = v[1] + sB2[c0 + 1];
            o.z = v[2] + sB2[c0 + 2];
            o.w = v[3] + sB2[c0 + 3];
            *(float4*)&zb[(r0 + r) * 128 + c0] = o;
        }
        __syncthreads();
        for (int idx = tid; idx < 64 * 64; idx += 256) {
            int r = idx >> 6, c = idx & 63;
            int rowAbs = row0 + r;
            float mu = zb[r * 128 + c];
            float lv = zb[r * 128 + 64 + c];
            float e = eps[(size_t)rowAbs * DD + c];
            float ey = mu + expf(lv * 0.5f) * e;
            outMu[(size_t)rowAbs * DD + c] = mu;
            outLv[(size_t)rowAbs * DD + c] = lv;
            __half hi = __float2half_rn(ey);
            __half lo = __float2half_rn(ey - __half2float(hi));
            unsigned char* tb = g_abf + (size_t)rowAbs * 256;
            *(__half*)(tb + c * 2) = hi;
            *(__half*)(tb + 128 + c * 2) = lo;
        }
    }
}

// ---------------------------------------------------------------------------
// Decoder v4: fp16 2-term, register-resident B, K truncation, M=256 tiles.
// kmax = i/16 + 1 (mask[k][i]==0 for k>i by DAG construction).
// grid = (64 i, 64 groups of 16 tiles of 256 rows). 8 warps:
//   warp w: nc = w&3 (64-col chunk), rh = w>>2 (128-row half), 8 mb steps.
// smem: sB1 @0 (1K), sW3 @1K, psum[2][256][4] @2048 (8K),
//       A0 @10240 (256x272=69632), A1 @79872. W' (256x144=36864) staged
//       transiently at @10240, consumed into regs, region reused by A0.
// Total = 149504 B.
// ---------------------------------------------------------------------------
#define RP_A  272
#define RP_W  144
#define SW_OFF  10240
#define SA0_OFF 10240
#define SA1_OFF 79872
#define PSUM_OFF 2048

__global__ __launch_bounds__(256, 1)
void dec_mma_kernel(const float* __restrict__ b1g,
                    const float* __restrict__ w3g,
                    const float* __restrict__ b3g,
                    float* __restrict__ outX,
                    float* __restrict__ outYr) {
    uint32_t sb = smem_u32(smemraw);
    float* sB1 = (float*)smemraw;
    float* sW3 = (float*)(smemraw + 1024);
    float* psum = (float*)(smemraw + PSUM_OFF);   // [2][256][4]
    int tid = threadIdx.x, wid = tid >> 5, lane = tid & 31;
    int i = blockIdx.x;
    int tile0 = blockIdx.y * 16;                  // in units of 256-row tiles
    int nc = wid & 3, rh = wid >> 2;
    const int kmax = (i >> 4) + 1;                // 1..4 k-steps of 16
    const int kc2 = 2 * kmax;                     // 16B chunks per (hi|lo) region

    // ---- stage W' fp16 (256 rows x kmax*32 B) ----
    {
        const unsigned char* src = g_wbf + (size_t)i * 32768;
#pragma unroll
        for (int c = 0; c < 8; c++)
            if (c < kc2)
                cp_async16(sb + SW_OFF + tid * RP_W + c * 16, src + tid * 128 + c * 16);
        CP_COMMIT();
        sB1[tid] = b1g[i * HID + tid];
        sW3[tid] = w3g[i * HID + tid];
    }
    float b3v = b3g[i];
    CP_WAIT0();
    __syncthreads();

    // ---- load this warp's B fragments into registers ----
    int r8 = lane & 7, g = lane >> 3;
    uint32_t Bh[4][16];
#pragma unroll
    for (int ks = 0; ks < 4; ks++)
#pragma unroll
        for (int q = 0; q < 16; q++) Bh[ks][q] = 0u;
    {
        uint32_t bRow = (uint32_t)((g >> 1) * 8 + r8);
        uint32_t bCol = (uint32_t)((g & 1) * 16);
        uint32_t bBase = sb + SW_OFF + (uint32_t)(nc * 64 + bRow) * RP_W + bCol;
#pragma unroll
        for (int ks = 0; ks < 4; ks++) {
            if (ks < kmax) {
#pragma unroll
                for (int tp = 0; tp < 4; tp++) {
                    uint32_t a = bBase + tp * 16 * RP_W + ks * 32;
                    ldsm_x4(a, Bh[ks][tp * 4], Bh[ks][tp * 4 + 1],
                            Bh[ks][tp * 4 + 2], Bh[ks][tp * 4 + 3]);
                }
            }
        }
    }
    __syncthreads();   // W' region free; A buffers may reuse it

    // ---- prefetch A tile 0 (256 rows, truncated to kmax, hi+lo regions) ----
    {
        const unsigned char* src = g_abf + (size_t)tile0 * 256 * 256;
#pragma unroll
        for (int c = 0; c < 8; c++) {
            if (c < kc2) {
                cp_async16(sb + SA0_OFF + tid * RP_A + c * 16, src + tid * 256 + c * 16);
                cp_async16(sb + SA0_OFF + tid * RP_A + 128 + c * 16, src + tid * 256 + 128 + c * 16);
            }
        }
        CP_COMMIT();
    }

    // per-lane A fragment address components
    uint32_t aRowBase = (uint32_t)(rh * 128 + (g & 1) * 8 + r8);
    uint32_t aCol = (uint32_t)((g >> 1) * 16);
    int cq = (lane & 3) * 2, rq = lane >> 2;

    for (int j = 0; j < 16; j++) {
        CP_WAIT0();
        __syncthreads();
        int buf = j & 1;
        if (j + 1 < 16) {
            const unsigned char* src = g_abf + (size_t)(tile0 + j + 1) * 256 * 256;
            uint32_t dstOff = buf ? SA0_OFF : SA1_OFF;
#pragma unroll
            for (int c = 0; c < 8; c++) {
                if (c < kc2) {
                    cp_async16(sb + dstOff + tid * RP_A + c * 16, src + tid * 256 + c * 16);
                    cp_async16(sb + dstOff + tid * RP_A + 128 + c * 16, src + tid * 256 + 128 + c * 16);
                }
            }
            CP_COMMIT();
        }

        uint32_t aTile = sb + (buf ? SA1_OFF : SA0_OFF);
#pragma unroll 1
        for (int mb = 0; mb < 8; mb++) {
            uint32_t aBase = aTile + (aRowBase + mb * 16) * RP_A + aCol;
            float acc[8][4];
#pragma unroll
            for (int t = 0; t < 8; t++)
#pragma unroll
                for (int q = 0; q < 4; q++) acc[t][q] = 0.f;

#pragma unroll
            for (int ks = 0; ks < 4; ks++) {
                if (ks < kmax) {
                    uint32_t Ah[4], Al[4];
                    ldsm_x4(aBase + ks * 32,       Ah[0], Ah[1], Ah[2], Ah[3]);
                    ldsm_x4(aBase + 128 + ks * 32, Al[0], Al[1], Al[2], Al[3]);
#pragma unroll
                    for (int nt = 0; nt < 8; nt++)
                        mma16816(acc[nt], Ah, Bh[ks][nt * 2], Bh[ks][nt * 2 + 1]);
#pragma unroll
                    for (int nt = 0; nt < 8; nt++)
                        mma16816(acc[nt], Al, Bh[ks][nt * 2], Bh[ks][nt * 2 + 1]);
                }
            }

            // fused relu + dot epilogue over this warp's 64-col chunk
            float p0 = 0.f, p1 = 0.f;
#pragma unroll
            for (int nt = 0; nt < 8; nt++) {
                int col = nc * 64 + nt * 8 + cq;
                float b1a = sB1[col], b1b = sB1[col + 1];
                float w3a = sW3[col], w3b = sW3[col + 1];
                p0 = fmaf(fmaxf(acc[nt][0] + b1a, 0.f), w3a, p0);
                p0 = fmaf(fmaxf(acc[nt][1] + b1b, 0.f), w3b, p0);
                p1 = fmaf(fmaxf(acc[nt][2] + b1a, 0.f), w3a, p1);
                p1 = fmaf(fmaxf(acc[nt][3] + b1b, 0.f), w3b, p1);
            }
#pragma unroll
            for (int off = 1; off <= 2; off <<= 1) {
                p0 += __shfl_xor_sync(0xFFFFFFFFu, p0, off);
                p1 += __shfl_xor_sync(0xFFFFFFFFu, p1, off);
            }
            if ((lane & 3) == 0) {
                int row = rh * 128 + mb * 16 + rq;
                psum[buf * 1024 + row * 4 + nc] = p0;
                psum[buf * 1024 + (row + 8) * 4 + nc] = p1;
            }
        }
        __syncthreads();
        {
            float o = psum[buf * 1024 + tid * 4 + 0] + psum[buf * 1024 + tid * 4 + 1] +
                      psum[buf * 1024 + tid * 4 + 2] + psum[buf * 1024 + tid * 4 + 3] + b3v;
            size_t grow = (size_t)(tile0 + j) * 256 + tid;
            outX[grow * 64 + i] = o;
            outYr[grow * 128 + i] = o;
        }
        // next iteration uses the other psum buffer; one sync per tile suffices
    }
}

// ---------------------------------------------------------------------------
extern "C" void kernel_launch(void* const* d_in, const int* in_sizes, int n_in,
                              void* d_out, int out_size) {
    const float* x      = (const float*)d_in[0];
    const float* eps    = (const float*)d_in[1];
    const float* enc1_w = (const float*)d_in[2];
    const float* enc1_b = (const float*)d_in[3];
    const float* enc3_w = (const float*)d_in[4];
    const float* enc3_b = (const float*)d_in[5];
    const float* dec1_w = (const float*)d_in[6];
    const float* dec1_b = (const float*)d_in[7];
    const float* dec3_w = (const float*)d_in[8];
    const float* dec3_b = (const float*)d_in[9];
    const unsigned char* bmask = (const unsigned char*)d_in[10];
    (void)n_in; (void)in_sizes; (void)out_size;

    float* out   = (float*)d_out;
    float* outX  = out;
    float* outMu = out + (size_t)BATCH * DD;
    float* outLv = out + (size_t)2 * BATCH * DD;
    float* outYr = out + (size_t)3 * BATCH * DD;

    size_t sEnc = (size_t)(32768 + DD * HID + HID + 128) * sizeof(float);  // 198,144
    size_t sDec = 149504;
    cudaFuncSetAttribute(enc_fused_kernel, cudaFuncAttributeMaxDynamicSharedMemorySize, (int)sEnc);
    cudaFuncSetAttribute(dec_mma_kernel,   cudaFuncAttributeMaxDynamicSharedMemorySize, (int)sDec);

    mask_expand_kernel<<<1, 256>>>(bmask);
    wprep_kernel<<<DD, 256>>>(dec1_w);
    zero_yr_kernel<<<(BATCH * 16) / 256, 256>>>((float4*)outYr);
    enc_fused_kernel<<<BATCH / 64, 256, sEnc>>>(x, eps, enc1_w, enc1_b,
                                                enc3_w, enc3_b, outMu, outLv);
    dec_mma_kernel<<<dim3(DD, NT256 / 16), 256, sDec>>>(dec1_b, dec3_w, dec3_b, outX, outYr);
}

// round 12
// speedup vs baseline: 1.9560x; 1.4322x over previous
#include <cuda_runtime.h>
#include <cuda_fp16.h>
#include <cstdint>

// ---------------------------------------------------------------------------
// CausalVAE2: B=262144, D=64, HID=256
// out layout: [x_out B*64][mu B*64][log_var B*64][y_recon B*128]
// Decoder: mma.sync fp16 SINGLE-term (A fp16, W fp16; error budget validated:
// W-1term measured 2.04e-4, A-1term adds ~same in quadrature => ~2.9e-4),
// register-resident B fragments, triangular-K truncation, M=256 tiles,
// 2 CTAs/SM.
// ---------------------------------------------------------------------------

#define BATCH 262144
#define DD 64
#define HID 256
#define NT256 (BATCH / 256)           // 1024 row tiles of 256

// Scratch (device globals)
// A': flat [row][k 0..63 fp16 (128B)]
__device__ __align__(16) unsigned char g_abf[(size_t)BATCH * 128];  // 32MB
// W' per i: [n 0..255][k fp16 128B]
__device__ __align__(16) unsigned char g_wbf[(size_t)DD * 32768];   // 2MB
__device__ int g_mask[DD * DD];

// ---- packed f32x2 helpers (encoder) ---------------------------------------
static __device__ __forceinline__ unsigned long long pk2(float lo, float hi) {
    unsigned long long r;
    asm("mov.b64 %0, {%1, %2};" : "=l"(r) : "f"(lo), "f"(hi));
    return r;
}
static __device__ __forceinline__ unsigned long long ffma2(unsigned long long a,
                                                           unsigned long long b,
                                                           unsigned long long c) {
    unsigned long long d;
    asm("fma.rn.f32x2 %0, %1, %2, %3;" : "=l"(d) : "l"(a), "l"(b), "l"(c));
    return d;
}
static __device__ __forceinline__ void upk2(unsigned long long v, float& lo, float& hi) {
    asm("mov.b64 {%0, %1}, %2;" : "=f"(lo), "=f"(hi) : "l"(v));
}

// ---- baseline tensor-core primitives --------------------------------------
static __device__ __forceinline__ uint32_t smem_u32(const void* p) {
    uint32_t a;
    asm("{ .reg .u64 t; cvta.to.shared.u64 t, %1; cvt.u32.u64 %0, t; }" : "=r"(a) : "l"(p));
    return a;
}
static __device__ __forceinline__ void ldsm_x4(uint32_t addr, uint32_t& r0, uint32_t& r1,
                                               uint32_t& r2, uint32_t& r3) {
    asm volatile("ldmatrix.sync.aligned.m8n8.x4.shared.b16 {%0,%1,%2,%3}, [%4];"
                 : "=r"(r0), "=r"(r1), "=r"(r2), "=r"(r3) : "r"(addr));
}
static __device__ __forceinline__ void mma16816(float* d, const uint32_t* a,
                                                uint32_t b0, uint32_t b1) {
    asm volatile("mma.sync.aligned.m16n8k16.row.col.f32.f16.f16.f32 "
                 "{%0,%1,%2,%3}, {%4,%5,%6,%7}, {%8,%9}, {%0,%1,%2,%3};"
                 : "+f"(d[0]), "+f"(d[1]), "+f"(d[2]), "+f"(d[3])
                 : "r"(a[0]), "r"(a[1]), "r"(a[2]), "r"(a[3]), "r"(b0), "r"(b1));
}
static __device__ __forceinline__ void cp_async16(uint32_t dst, const void* src) {
    asm volatile("cp.async.cg.shared.global [%0], [%1], 16;" :: "r"(dst), "l"(src));
}
#define CP_COMMIT() asm volatile("cp.async.commit_group;" ::: "memory")
#define CP_WAIT0()  asm volatile("cp.async.wait_group 0;" ::: "memory")

extern __shared__ __align__(1024) char smemraw[];

// ---------------------------------------------------------------------------
// Mask decode (robust to bool delivered as u8 / i32 / f32)
// ---------------------------------------------------------------------------
__global__ void mask_expand_kernel(const unsigned char* __restrict__ mb) {
    __shared__ int flags[2];
    __shared__ int s_mode;
    int tid = threadIdx.x;
    if (tid < 2) flags[tid] = 0;
    __syncthreads();
    for (int idx = tid; idx < DD * DD; idx += blockDim.x) {
        unsigned char b = mb[idx];
        if ((idx & 3) != 0 && b != 0) {
            atomicOr(&flags[1], 1);
            if (b > 1) atomicOr(&flags[0], 1);
        }
    }
    __syncthreads();
    if (tid == 0) s_mode = flags[0] ? 2 : (flags[1] ? 1 : 0);
    __syncthreads();
    int mode = s_mode;
    for (int idx = tid; idx < DD * DD; idx += blockDim.x) {
        int v;
        if (mode == 2)      v = (((const float*)mb)[idx] != 0.0f);
        else if (mode == 1) v = (mb[idx] != 0);
        else                v = (((const int*)mb)[idx] != 0);
        g_mask[idx] = v;
    }
}

// ---------------------------------------------------------------------------
// W-prep: per i, masked dec1_w -> fp16, layout [n][k 0..63].
// ---------------------------------------------------------------------------
__global__ void wprep_kernel(const float* __restrict__ w1g) {
    int i = blockIdx.x, tid = threadIdx.x;
    unsigned char* wb = g_wbf + (size_t)i * 32768;
    for (int idx = tid; idx < DD * HID; idx += blockDim.x) {
        int k = idx >> 8, n = idx & 255;
        float m = (float)g_mask[k * DD + i];
        float w = w1g[(size_t)i * DD * HID + (size_t)k * HID + n] * m;
        *(__half*)(wb + n * 128 + k * 2) = __float2half_rn(w);
    }
}

__global__ void zero_yr_kernel(float4* __restrict__ yr) {
    size_t idx = (size_t)blockIdx.x * blockDim.x + threadIdx.x;
    size_t row = idx >> 4;
    int c4 = (int)(idx & 15);
    yr[row * 32 + 16 + c4] = make_float4(0.f, 0.f, 0.f, 0.f);
}

// ---------------------------------------------------------------------------
// Fused encoder (f32x2). Epilogue emits eps_y as single fp16 rows in g_abf.
// ---------------------------------------------------------------------------
__global__ __launch_bounds__(256, 1) void enc_fused_kernel(const float* __restrict__ x,
                                                           const float* __restrict__ eps,
                                                           const float* __restrict__ w1g,
                                                           const float* __restrict__ b1g,
                                                           const float* __restrict__ w2g,
                                                           const float* __restrict__ b2g,
                                                           float* __restrict__ outMu,
                                                           float* __restrict__ outLv) {
    float* smem = (float*)smemraw;
    float* sR0  = smem;                  // 32768 floats
    float* sW1  = sR0;                   // [64][256]
    float* sXT  = sR0 + DD * HID;        // [64][65]
    float* hbuf = sR0 + 32768;           // [64][256]
    float* sB1  = hbuf + DD * HID;       // 256
    float* sB2  = sB1 + HID;             // 128
    int tid = threadIdx.x;
    int row0 = blockIdx.x * 64;

    {
        const float4* w4 = (const float4*)w1g;
        float4* sW4 = (float4*)sW1;
#pragma unroll
        for (int t = 0; t < 16; t++) sW4[tid + 256 * t] = w4[tid + 256 * t];
        sB1[tid] = b1g[tid];
        if (tid < 128) sB2[tid] = b2g[tid];
        for (int idx = tid; idx < 64 * DD; idx += 256) {
            int r = idx >> 6, k = idx & 63;
            sXT[k * 65 + r] = x[(size_t)(row0 + r) * DD + k];
        }
    }
    __syncthreads();

    int cg = tid & 31, rg = tid >> 5;

    // GEMM1: h = relu(x@W1+b1)
    {
        int c0 = cg * 8, r0 = rg * 8;
        unsigned long long acc[8][4];
#pragma unroll
        for (int r = 0; r < 8; r++)
#pragma unroll
            for (int j = 0; j < 4; j++) acc[r][j] = 0ull;
        for (int k = 0; k < DD; k++) {
            float4 wa = *(const float4*)&sW1[k * HID + c0];
            float4 wb = *(const float4*)&sW1[k * HID + c0 + 4];
            unsigned long long w2[4];
            w2[0] = pk2(wa.x, wa.y); w2[1] = pk2(wa.z, wa.w);
            w2[2] = pk2(wb.x, wb.y); w2[3] = pk2(wb.z, wb.w);
#pragma unroll
            for (int r = 0; r < 8; r++) {
                float e = sXT[k * 65 + r0 + r];
                unsigned long long e2 = pk2(e, e);
#pragma unroll
                for (int j = 0; j < 4; j++) acc[r][j] = ffma2(e2, w2[j], acc[r][j]);
            }
        }
        __syncthreads();
#pragma unroll
        for (int r = 0; r < 8; r++) {
            float v[8];
#pragma unroll
            for (int j = 0; j < 4; j++) upk2(acc[r][j], v[2 * j], v[2 * j + 1]);
            float4 o1, o2;
            o1.x = fmaxf(v[0] + sB1[c0 + 0], 0.f);
            o1.y = fmaxf(v[1] + sB1[c0 + 1], 0.f);
            o1.z = fmaxf(v[2] + sB1[c0 + 2], 0.f);
            o1.w = fmaxf(v[3] + sB1[c0 + 3], 0.f);
            o2.x = fmaxf(v[4] + sB1[c0 + 4], 0.f);
            o2.y = fmaxf(v[5] + sB1[c0 + 5], 0.f);
            o2.z = fmaxf(v[6] + sB1[c0 + 6], 0.f);
            o2.w = fmaxf(v[7] + sB1[c0 + 7], 0.f);
            *(float4*)&hbuf[(r0 + r) * HID + c0] = o1;
            *(float4*)&hbuf[(r0 + r) * HID + c0 + 4] = o2;
        }
    }

    // W2 overwrite
    {
        const float4* w4 = (const float4*)w2g;
        float4* sW4 = (float4*)sR0;
#pragma unroll
        for (int t = 0; t < 32; t++) sW4[tid + 256 * t] = w4[tid + 256 * t];
    }
    __syncthreads();

    // GEMM2 + epilogue
    {
        int c0 = cg * 4, r0 = rg * 8;
        unsigned long long acc[8][2];
#pragma unroll
        for (int r = 0; r < 8; r++) { acc[r][0] = 0ull; acc[r][1] = 0ull; }
        for (int k = 0; k < HID; k++) {
            float4 wa = *(const float4*)&sR0[k * 128 + c0];
            unsigned long long w20 = pk2(wa.x, wa.y), w21 = pk2(wa.z, wa.w);
#pragma unroll
            for (int r = 0; r < 8; r++) {
                float e = hbuf[(r0 + r) * HID + k];
                unsigned long long e2 = pk2(e, e);
                acc[r][0] = ffma2(e2, w20, acc[r][0]);
                acc[r][1] = ffma2(e2, w21, acc[r][1]);
            }
        }
        __syncthreads();
        float* zb = hbuf;
#pragma unroll
        for (int r = 0; r < 8; r++) {
            float v[4];
            upk2(acc[r][0], v[0], v[1]);
            upk2(acc[r][1], v[2], v[3]);
            float4 o;
            o.x = v[0] + sB2[c0 + 0];
            o.y = v[1] + sB2[c0 + 1];
            o.z = v[2] + sB2[c0 + 2];
            o.w = v[3] + sB2[c0 + 3];
            *(float4*)&zb[(r0 + r) * 128 + c0] = o;
        }
        __syncthreads();
        for (int idx = tid; idx < 64 * 64; idx += 256) {
            int r = idx >> 6, c = idx & 63;
            int rowAbs = row0 + r;
            float mu = zb[r * 128 + c];
            float lv = zb[r * 128 + 64 + c];
            float e = eps[(size_t)rowAbs * DD + c];
            float ey = mu + expf(lv * 0.5f) * e;
            outMu[(size_t)rowAbs * DD + c] = mu;
            outLv[(size_t)rowAbs * DD + c] = lv;
            *(__half*)(g_abf + (size_t)rowAbs * 128 + c * 2) = __float2half_rn(ey);
        }
    }
}

// ---------------------------------------------------------------------------
// Decoder v5: fp16 1-term, register-resident B, K truncation, M=256 tiles,
// 2 CTAs/SM. kmax = i/16 + 1 (mask[k][i]==0 for k>i by DAG construction).
// grid = (64 i, 64 groups of 16 tiles of 256 rows). 8 warps:
//   warp w: nc = w&3 (64-col chunk), rh = w>>2 (128-row half), 8 mb steps.
// smem: sB1 @0 (1K), sW3 @1K, psum[2][256][4] @2048 (8K),
//       A0 @10240 (256x144=36864), A1 @47104. W' (256x144) staged transiently
//       at @10240 (== A0), consumed into regs, region reused by A0.
// Total = 83968 B -> 2 CTAs/SM.
// ---------------------------------------------------------------------------
#define RP_A  144
#define RP_W  144
#define SW_OFF  10240
#define SA0_OFF 10240
#define SA1_OFF 47104
#define PSUM_OFF 2048

__global__ __launch_bounds__(256, 2)
void dec_mma_kernel(const float* __restrict__ b1g,
                    const float* __restrict__ w3g,
                    const float* __restrict__ b3g,
                    float* __restrict__ outX,
                    float* __restrict__ outYr) {
    uint32_t sb = smem_u32(smemraw);
    float* sB1 = (float*)smemraw;
    float* sW3 = (float*)(smemraw + 1024);
    float* psum = (float*)(smemraw + PSUM_OFF);   // [2][256][4]
    int tid = threadIdx.x, wid = tid >> 5, lane = tid & 31;
    int i = blockIdx.x;
    int tile0 = blockIdx.y * 16;                  // in units of 256-row tiles
    int nc = wid & 3, rh = wid >> 2;
    const int kmax = (i >> 4) + 1;                // 1..4 k-steps of 16
    const int kc2 = 2 * kmax;                     // 16B chunks to stage per row

    // ---- stage W' fp16 (256 rows x kmax*32 B) ----
    {
        const unsigned char* src = g_wbf + (size_t)i * 32768;
#pragma unroll
        for (int c = 0; c < 8; c++)
            if (c < kc2)
                cp_async16(sb + SW_OFF + tid * RP_W + c * 16, src + tid * 128 + c * 16);
        CP_COMMIT();
        sB1[tid] = b1g[i * HID + tid];
        sW3[tid] = w3g[i * HID + tid];
    }
    float b3v = b3g[i];
    CP_WAIT0();
    __syncthreads();

    // ---- load this warp's B fragments into registers ----
    int r8 = lane & 7, g = lane >> 3;
    uint32_t Bh[4][16];
#pragma unroll
    for (int ks = 0; ks < 4; ks++)
#pragma unroll
        for (int q = 0; q < 16; q++) Bh[ks][q] = 0u;
    {
        uint32_t bRow = (uint32_t)((g >> 1) * 8 + r8);
        uint32_t bCol = (uint32_t)((g & 1) * 16);
        uint32_t bBase = sb + SW_OFF + (uint32_t)(nc * 64 + bRow) * RP_W + bCol;
#pragma unroll
        for (int ks = 0; ks < 4; ks++) {
            if (ks < kmax) {
#pragma unroll
                for (int tp = 0; tp < 4; tp++) {
                    uint32_t a = bBase + tp * 16 * RP_W + ks * 32;
                    ldsm_x4(a, Bh[ks][tp * 4], Bh[ks][tp * 4 + 1],
                            Bh[ks][tp * 4 + 2], Bh[ks][tp * 4 + 3]);
                }
            }
        }
    }
    __syncthreads();   // W' region free; A buffers may reuse it

    // ---- prefetch A tile 0 (256 rows, truncated to kmax) ----
    {
        const unsigned char* src = g_abf + (size_t)tile0 * 256 * 128;
#pragma unroll
        for (int c = 0; c < 8; c++)
            if (c < kc2)
                cp_async16(sb + SA0_OFF + tid * RP_A + c * 16, src + tid * 128 + c * 16);
        CP_COMMIT();
    }

    // per-lane A fragment address components
    uint32_t aRowBase = (uint32_t)(rh * 128 + (g & 1) * 8 + r8);
    uint32_t aCol = (uint32_t)((g >> 1) * 16);
    int cq = (lane & 3) * 2, rq = lane >> 2;

    for (int j = 0; j < 16; j++) {
        CP_WAIT0();
        __syncthreads();
        int buf = j & 1;
        if (j + 1 < 16) {
            const unsigned char* src = g_abf + (size_t)(tile0 + j + 1) * 256 * 128;
            uint32_t dstOff = buf ? SA0_OFF : SA1_OFF;
#pragma unroll
            for (int c = 0; c < 8; c++)
                if (c < kc2)
                    cp_async16(sb + dstOff + tid * RP_A + c * 16, src + tid * 128 + c * 16);
            CP_COMMIT();
        }

        uint32_t aTile = sb + (buf ? SA1_OFF : SA0_OFF);
#pragma unroll 1
        for (int mb = 0; mb < 8; mb++) {
            uint32_t aBase = aTile + (aRowBase + mb * 16) * RP_A + aCol;
            float acc[8][4];
#pragma unroll
            for (int t = 0; t < 8; t++)
#pragma unroll
                for (int q = 0; q < 4; q++) acc[t][q] = 0.f;

#pragma unroll
            for (int ks = 0; ks < 4; ks++) {
                if (ks < kmax) {
                    uint32_t Ah[4];
                    ldsm_x4(aBase + ks * 32, Ah[0], Ah[1], Ah[2], Ah[3]);
#pragma unroll
                    for (int nt = 0; nt < 8; nt++)
                        mma16816(acc[nt], Ah, Bh[ks][nt * 2], Bh[ks][nt * 2 + 1]);
                }
            }

            // fused relu + dot epilogue over this warp's 64-col chunk
            float p0 = 0.f, p1 = 0.f;
#pragma unroll
            for (int nt = 0; nt < 8; nt++) {
                int col = nc * 64 + nt * 8 + cq;
                float b1a = sB1[col], b1b = sB1[col + 1];
                float w3a = sW3[col], w3b = sW3[col + 1];
                p0 = fmaf(fmaxf(acc[nt][0] + b1a, 0.f), w3a, p0);
                p0 = fmaf(fmaxf(acc[nt][1] + b1b, 0.f), w3b, p0);
                p1 = fmaf(fmaxf(acc[nt][2] + b1a, 0.f), w3a, p1);
                p1 = fmaf(fmaxf(acc[nt][3] + b1b, 0.f), w3b, p1);
            }
#pragma unroll
            for (int off = 1; off <= 2; off <<= 1) {
                p0 += __shfl_xor_sync(0xFFFFFFFFu, p0, off);
                p1 += __shfl_xor_sync(0xFFFFFFFFu, p1, off);
            }
            if ((lane & 3) == 0) {
                int row = rh * 128 + mb * 16 + rq;
                psum[buf * 1024 + row * 4 + nc] = p0;
                psum[buf * 1024 + (row + 8) * 4 + nc] = p1;
            }
        }
        __syncthreads();
        {
            float o = psum[buf * 1024 + tid * 4 + 0] + psum[buf * 1024 + tid * 4 + 1] +
                      psum[buf * 1024 + tid * 4 + 2] + psum[buf * 1024 + tid * 4 + 3] + b3v;
            size_t grow = (size_t)(tile0 + j) * 256 + tid;
            outX[grow * 64 + i] = o;
            outYr[grow * 128 + i] = o;
        }
        // next iteration uses the other psum buffer; one sync per tile suffices
    }
}

// ---------------------------------------------------------------------------
extern "C" void kernel_launch(void* const* d_in, const int* in_sizes, int n_in,
                              void* d_out, int out_size) {
    const float* x      = (const float*)d_in[0];
    const float* eps    = (const float*)d_in[1];
    const float* enc1_w = (const float*)d_in[2];
    const float* enc1_b = (const float*)d_in[3];
    const float* enc3_w = (const float*)d_in[4];
    const float* enc3_b = (const float*)d_in[5];
    const float* dec1_w = (const float*)d_in[6];
    const float* dec1_b = (const float*)d_in[7];
    const float* dec3_w = (const float*)d_in[8];
    const float* dec3_b = (const float*)d_in[9];
    const unsigned char* bmask = (const unsigned char*)d_in[10];
    (void)n_in; (void)in_sizes; (void)out_size;

    float* out   = (float*)d_out;
    float* outX  = out;
    float* outMu = out + (size_t)BATCH * DD;
    float* outLv = out + (size_t)2 * BATCH * DD;
    float* outYr = out + (size_t)3 * BATCH * DD;

    size_t sEnc = (size_t)(32768 + DD * HID + HID + 128) * sizeof(float);  // 198,144
    size_t sDec = 83968;
    cudaFuncSetAttribute(enc_fused_kernel, cudaFuncAttributeMaxDynamicSharedMemorySize, (int)sEnc);
    cudaFuncSetAttribute(dec_mma_kernel,   cudaFuncAttributeMaxDynamicSharedMemorySize, (int)sDec);

    mask_expand_kernel<<<1, 256>>>(bmask);
    wprep_kernel<<<DD, 256>>>(dec1_w);
    zero_yr_kernel<<<(BATCH * 16) / 256, 256>>>((float4*)outYr);
    enc_fused_kernel<<<BATCH / 64, 256, sEnc>>>(x, eps, enc1_w, enc1_b,
                                                enc3_w, enc3_b, outMu, outLv);
    dec_mma_kernel<<<dim3(DD, NT256 / 16), 256, sDec>>>(dec1_b, dec3_w, dec3_b, outX, outYr);
}

// round 13
// speedup vs baseline: 2.6874x; 1.3739x over previous
#include <cuda_runtime.h>
#include <cuda_fp16.h>
#include <cstdint>

// ---------------------------------------------------------------------------
// CausalVAE2: B=262144, D=64, HID=256
// out layout: [x_out B*64][mu B*64][log_var B*64][y_recon B*128]
// Encoder AND decoder on mma.sync fp16 (1-term; quadrature error model
// validated R9/R12). Decoder: register-resident B, triangular-K truncation,
// M=256 tiles, 2 CTAs/SM (R12, unchanged).
// ---------------------------------------------------------------------------

#define BATCH 262144
#define DD 64
#define HID 256
#define NT256 (BATCH / 256)           // 1024 row tiles of 256

// Scratch (device globals)
__device__ __align__(16) unsigned char g_abf[(size_t)BATCH * 128];  // 32MB eps_y fp16 [row][64k]
__device__ __align__(16) unsigned char g_xf16[(size_t)BATCH * 128]; // 32MB x fp16 [row][64k]
__device__ __align__(16) unsigned char g_wbf[(size_t)DD * 32768];   // 2MB dec W' [n][k] fp16
__device__ __align__(16) unsigned char g_ew1[256 * 128];            // enc W1 B-layout [n=256][k=64] fp16
__device__ __align__(16) unsigned char g_ew2[128 * 512];            // enc W2 B-layout [n=128][k=256] fp16
__device__ int g_mask[DD * DD];

// ---- baseline tensor-core primitives --------------------------------------
static __device__ __forceinline__ uint32_t smem_u32(const void* p) {
    uint32_t a;
    asm("{ .reg .u64 t; cvta.to.shared.u64 t, %1; cvt.u32.u64 %0, t; }" : "=r"(a) : "l"(p));
    return a;
}
static __device__ __forceinline__ void ldsm_x4(uint32_t addr, uint32_t& r0, uint32_t& r1,
                                               uint32_t& r2, uint32_t& r3) {
    asm volatile("ldmatrix.sync.aligned.m8n8.x4.shared.b16 {%0,%1,%2,%3}, [%4];"
                 : "=r"(r0), "=r"(r1), "=r"(r2), "=r"(r3) : "r"(addr));
}
static __device__ __forceinline__ void mma16816(float* d, const uint32_t* a,
                                                uint32_t b0, uint32_t b1) {
    asm volatile("mma.sync.aligned.m16n8k16.row.col.f32.f16.f16.f32 "
                 "{%0,%1,%2,%3}, {%4,%5,%6,%7}, {%8,%9}, {%0,%1,%2,%3};"
                 : "+f"(d[0]), "+f"(d[1]), "+f"(d[2]), "+f"(d[3])
                 : "r"(a[0]), "r"(a[1]), "r"(a[2]), "r"(a[3]), "r"(b0), "r"(b1));
}
static __device__ __forceinline__ void cp_async16(uint32_t dst, const void* src) {
    asm volatile("cp.async.cg.shared.global [%0], [%1], 16;" :: "r"(dst), "l"(src));
}
#define CP_COMMIT() asm volatile("cp.async.commit_group;" ::: "memory")
#define CP_WAIT0()  asm volatile("cp.async.wait_group 0;" ::: "memory")

extern __shared__ __align__(1024) char smemraw[];

// ---------------------------------------------------------------------------
// Mask decode (robust to bool delivered as u8 / i32 / f32)
// ---------------------------------------------------------------------------
__global__ void mask_expand_kernel(const unsigned char* __restrict__ mb) {
    __shared__ int flags[2];
    __shared__ int s_mode;
    int tid = threadIdx.x;
    if (tid < 2) flags[tid] = 0;
    __syncthreads();
    for (int idx = tid; idx < DD * DD; idx += blockDim.x) {
        unsigned char b = mb[idx];
        if ((idx & 3) != 0 && b != 0) {
            atomicOr(&flags[1], 1);
            if (b > 1) atomicOr(&flags[0], 1);
        }
    }
    __syncthreads();
    if (tid == 0) s_mode = flags[0] ? 2 : (flags[1] ? 1 : 0);
    __syncthreads();
    int mode = s_mode;
    for (int idx = tid; idx < DD * DD; idx += blockDim.x) {
        int v;
        if (mode == 2)      v = (((const float*)mb)[idx] != 0.0f);
        else if (mode == 1) v = (mb[idx] != 0);
        else                v = (((const int*)mb)[idx] != 0);
        g_mask[idx] = v;
    }
}

// ---------------------------------------------------------------------------
// Decoder W-prep: masked dec1_w -> fp16, layout [n][k].
// ---------------------------------------------------------------------------
__global__ void wprep_kernel(const float* __restrict__ w1g) {
    int i = blockIdx.x, tid = threadIdx.x;
    unsigned char* wb = g_wbf + (size_t)i * 32768;
    for (int idx = tid; idx < DD * HID; idx += blockDim.x) {
        int k = idx >> 8, n = idx & 255;
        float m = (float)g_mask[k * DD + i];
        float w = w1g[(size_t)i * DD * HID + (size_t)k * HID + n] * m;
        *(__half*)(wb + n * 128 + k * 2) = __float2half_rn(w);
    }
}

// ---------------------------------------------------------------------------
// Encoder W-prep: enc1_w [k=64][n=256] -> g_ew1 [n][k]; enc3_w [k=256][n=128]
// -> g_ew2 [n][k]. fp16.
// ---------------------------------------------------------------------------
__global__ void ewprep_kernel(const float* __restrict__ w1,
                              const float* __restrict__ w2) {
    int t = blockIdx.x * 256 + threadIdx.x;
    int stride = gridDim.x * 256;
    for (int idx = t; idx < 64 * 256; idx += stride) {
        int n = idx >> 6, k = idx & 63;
        *(__half*)(g_ew1 + n * 128 + k * 2) = __float2half_rn(w1[k * 256 + n]);
    }
    for (int idx = t; idx < 256 * 128; idx += stride) {
        int n = idx >> 8, k = idx & 255;
        *(__half*)(g_ew2 + n * 512 + k * 2) = __float2half_rn(w2[k * 128 + n]);
    }
}

// ---------------------------------------------------------------------------
// x fp32 -> fp16 rows [row][64k]
// ---------------------------------------------------------------------------
__global__ void xprep_kernel(const float2* __restrict__ x) {
    size_t idx = (size_t)blockIdx.x * blockDim.x + threadIdx.x;  // B*32 float2
    float2 v = x[idx];
    ((__half2*)g_xf16)[idx] = __floats2half2_rn(v.x, v.y);
}

__global__ void zero_yr_kernel(float4* __restrict__ yr) {
    size_t idx = (size_t)blockIdx.x * blockDim.x + threadIdx.x;
    size_t row = idx >> 4;
    int c4 = (int)(idx & 15);
    yr[row * 32 + 16 + c4] = make_float4(0.f, 0.f, 0.f, 0.f);
}

// ---------------------------------------------------------------------------
// Tensor-core fused encoder: 256 rows/CTA, fp16 GEMM1 (relu) + GEMM2, epilogue
// mu/lv/eps_y. smem (bytes):
//  sB1e @0 (1024), sB2e @1024 (512; region to 1536)
//  sW1B @1536:   256 x 144  = 36864   (W1 B-layout, pad 144)
//  sW2B @38400:  128 x 528  = 67584   (W2 B-layout, pad 528)
//  sX   @105984: 256 x 144  = 36864   (x fp16 rows, pad 144)
//  sH   @142848:  64 x 528  = 33792   (H fp16 per 64-row sub-block; reused as
//                                      Z fp32 [64][128] after GEMM2)
// Total 176640.
// ---------------------------------------------------------------------------
#define E_SB1 0
#define E_SB2 1024
#define E_SW1 1536
#define E_SW2 38400
#define E_SX  105984
#define E_SH  142848

__global__ __launch_bounds__(256, 1)
void enc_mma_kernel(const float* __restrict__ eps,
                    const float* __restrict__ b1g,
                    const float* __restrict__ b2g,
                    float* __restrict__ outMu,
                    float* __restrict__ outLv) {
    uint32_t sb = smem_u32(smemraw);
    float* sB1e = (float*)(smemraw + E_SB1);
    float* sB2e = (float*)(smemraw + E_SB2);
    int tid = threadIdx.x, wid = tid >> 5, lane = tid & 31;
    int row0 = blockIdx.x * 256;
    int r8 = lane & 7, g = lane >> 3;
    int mt = wid & 3, nh = wid >> 2;
    int cq = (lane & 3) * 2, rq = lane >> 2;

    // ---- stage weights + x tile + biases ----
    sB1e[tid] = b1g[tid];
    if (tid < 128) sB2e[tid] = b2g[tid];
#pragma unroll
    for (int c = 0; c < 8; c++)
        cp_async16(sb + E_SW1 + tid * 144 + c * 16, g_ew1 + tid * 128 + c * 16);
#pragma unroll
    for (int c = 0; c < 16; c++)
        cp_async16(sb + E_SW2 + (tid >> 1) * 528 + (tid & 1) * 256 + c * 16,
                   g_ew2 + (tid >> 1) * 512 + (tid & 1) * 256 + c * 16);
#pragma unroll
    for (int c = 0; c < 8; c++)
        cp_async16(sb + E_SX + tid * 144 + c * 16,
                   g_xf16 + (size_t)(row0 + tid) * 128 + c * 16);
    CP_COMMIT();
    CP_WAIT0();
    __syncthreads();

    for (int sbk = 0; sbk < 4; sbk++) {
        if (sbk) __syncthreads();   // prev epilogue's sZ reads done before sH overwrite

        // ---- GEMM1: rows sbk*64 + mt*16, cols nh*128 (N=256, K=64) ----
        float acc1[16][4];
#pragma unroll
        for (int t = 0; t < 16; t++)
#pragma unroll
            for (int q = 0; q < 4; q++) acc1[t][q] = 0.f;
        {
            uint32_t aBase = sb + E_SX + (uint32_t)(sbk * 64 + mt * 16 + (g & 1) * 8 + r8) * 144
                             + (uint32_t)((g >> 1) * 16);
            uint32_t bBase = sb + E_SW1 + (uint32_t)(nh * 128 + (g >> 1) * 8 + r8) * 144
                             + (uint32_t)((g & 1) * 16);
#pragma unroll
            for (int ks = 0; ks < 4; ks++) {
                uint32_t Ah[4];
                ldsm_x4(aBase + ks * 32, Ah[0], Ah[1], Ah[2], Ah[3]);
#pragma unroll
                for (int tp = 0; tp < 8; tp++) {
                    uint32_t Bq[4];
                    ldsm_x4(bBase + tp * 16 * 144 + ks * 32, Bq[0], Bq[1], Bq[2], Bq[3]);
                    mma16816(acc1[tp * 2], Ah, Bq[0], Bq[1]);
                    mma16816(acc1[tp * 2 + 1], Ah, Bq[2], Bq[3]);
                }
            }
        }
        // relu + b1 -> sH fp16
#pragma unroll
        for (int nt = 0; nt < 16; nt++) {
            int col = nh * 128 + nt * 8 + cq;
            float b1a = sB1e[col], b1b = sB1e[col + 1];
            int row = mt * 16 + rq;
            __half2 h01 = __floats2half2_rn(fmaxf(acc1[nt][0] + b1a, 0.f),
                                            fmaxf(acc1[nt][1] + b1b, 0.f));
            __half2 h23 = __floats2half2_rn(fmaxf(acc1[nt][2] + b1a, 0.f),
                                            fmaxf(acc1[nt][3] + b1b, 0.f));
            *(__half2*)(smemraw + E_SH + row * 528 + col * 2) = h01;
            *(__half2*)(smemraw + E_SH + (row + 8) * 528 + col * 2) = h23;
        }
        __syncthreads();

        // ---- GEMM2: rows mt*16 of sub-block, cols nh*64 (N=128, K=256) ----
        float acc2[8][4];
#pragma unroll
        for (int t = 0; t < 8; t++)
#pragma unroll
            for (int q = 0; q < 4; q++) acc2[t][q] = 0.f;
        {
            uint32_t aBase = sb + E_SH + (uint32_t)(mt * 16 + (g & 1) * 8 + r8) * 528
                             + (uint32_t)((g >> 1) * 16);
            uint32_t bBase = sb + E_SW2 + (uint32_t)(nh * 64 + (g >> 1) * 8 + r8) * 528
                             + (uint32_t)((g & 1) * 16);
#pragma unroll
            for (int ks = 0; ks < 16; ks++) {
                uint32_t Ah[4];
                ldsm_x4(aBase + ks * 32, Ah[0], Ah[1], Ah[2], Ah[3]);
#pragma unroll
                for (int tp = 0; tp < 4; tp++) {
                    uint32_t Bq[4];
                    ldsm_x4(bBase + tp * 16 * 528 + ks * 32, Bq[0], Bq[1], Bq[2], Bq[3]);
                    mma16816(acc2[tp * 2], Ah, Bq[0], Bq[1]);
                    mma16816(acc2[tp * 2 + 1], Ah, Bq[2], Bq[3]);
                }
            }
        }
        __syncthreads();   // all sH reads done; reuse region as Z fp32 [64][128]
#pragma unroll
        for (int nt = 0; nt < 8; nt++) {
            int col = nh * 64 + nt * 8 + cq;
            float b2a = sB2e[col], b2b = sB2e[col + 1];
            int row = mt * 16 + rq;
            *(float2*)(smemraw + E_SH + row * 528 + col * 4) =
                make_float2(acc2[nt][0] + b2a, acc2[nt][1] + b2b);
            *(float2*)(smemraw + E_SH + (row + 8) * 528 + col * 4) =
                make_float2(acc2[nt][2] + b2a, acc2[nt][3] + b2b);
        }
        __syncthreads();

        // ---- epilogue: mu/lv/eps_y ----
        for (int idx = tid; idx < 64 * 64; idx += 256) {
            int r = idx >> 6, c = idx & 63;
            size_t rowAbs = (size_t)row0 + sbk * 64 + r;
            float mu = *(const float*)(smemraw + E_SH + r * 528 + c * 4);
            float lv = *(const float*)(smemraw + E_SH + r * 528 + (64 + c) * 4);
            float e = eps[rowAbs * DD + c];
            float ey = mu + expf(lv * 0.5f) * e;
            outMu[rowAbs * DD + c] = mu;
            outLv[rowAbs * DD + c] = lv;
            *(__half*)(g_abf + rowAbs * 128 + c * 2) = __float2half_rn(ey);
        }
    }
}

// ---------------------------------------------------------------------------
// Decoder v5 (R12, unchanged): fp16 1-term, register-resident B, K truncation,
// M=256 tiles, 2 CTAs/SM. kmax = i/16 + 1.
// ---------------------------------------------------------------------------
#define RP_A  144
#define RP_W  144
#define SW_OFF  10240
#define SA0_OFF 10240
#define SA1_OFF 47104
#define PSUM_OFF 2048

__global__ __launch_bounds__(256, 2)
void dec_mma_kernel(const float* __restrict__ b1g,
                    const float* __restrict__ w3g,
                    const float* __restrict__ b3g,
                    float* __restrict__ outX,
                    float* __restrict__ outYr) {
    uint32_t sb = smem_u32(smemraw);
    float* sB1 = (float*)smemraw;
    float* sW3 = (float*)(smemraw + 1024);
    float* psum = (float*)(smemraw + PSUM_OFF);   // [2][256][4]
    int tid = threadIdx.x, wid = tid >> 5, lane = tid & 31;
    int i = blockIdx.x;
    int tile0 = blockIdx.y * 16;
    int nc = wid & 3, rh = wid >> 2;
    const int kmax = (i >> 4) + 1;
    const int kc2 = 2 * kmax;

    {
        const unsigned char* src = g_wbf + (size_t)i * 32768;
#pragma unroll
        for (int c = 0; c < 8; c++)
            if (c < kc2)
                cp_async16(sb + SW_OFF + tid * RP_W + c * 16, src + tid * 128 + c * 16);
        CP_COMMIT();
        sB1[tid] = b1g[i * HID + tid];
        sW3[tid] = w3g[i * HID + tid];
    }
    float b3v = b3g[i];
    CP_WAIT0();
    __syncthreads();

    int r8 = lane & 7, g = lane >> 3;
    uint32_t Bh[4][16];
#pragma unroll
    for (int ks = 0; ks < 4; ks++)
#pragma unroll
        for (int q = 0; q < 16; q++) Bh[ks][q] = 0u;
    {
        uint32_t bRow = (uint32_t)((g >> 1) * 8 + r8);
        uint32_t bCol = (uint32_t)((g & 1) * 16);
        uint32_t bBase = sb + SW_OFF + (uint32_t)(nc * 64 + bRow) * RP_W + bCol;
#pragma unroll
        for (int ks = 0; ks < 4; ks++) {
            if (ks < kmax) {
#pragma unroll
                for (int tp = 0; tp < 4; tp++) {
                    uint32_t a = bBase + tp * 16 * RP_W + ks * 32;
                    ldsm_x4(a, Bh[ks][tp * 4], Bh[ks][tp * 4 + 1],
                            Bh[ks][tp * 4 + 2], Bh[ks][tp * 4 + 3]);
                }
            }
        }
    }
    __syncthreads();

    {
        const unsigned char* src = g_abf + (size_t)tile0 * 256 * 128;
#pragma unroll
        for (int c = 0; c < 8; c++)
            if (c < kc2)
                cp_async16(sb + SA0_OFF + tid * RP_A + c * 16, src + tid * 128 + c * 16);
        CP_COMMIT();
    }

    uint32_t aRowBase = (uint32_t)(rh * 128 + (g & 1) * 8 + r8);
    uint32_t aCol = (uint32_t)((g >> 1) * 16);
    int cq = (lane & 3) * 2, rq = lane >> 2;

    for (int j = 0; j < 16; j++) {
        CP_WAIT0();
        __syncthreads();
        int buf = j & 1;
        if (j + 1 < 16) {
            const unsigned char* src = g_abf + (size_t)(tile0 + j + 1) * 256 * 128;
            uint32_t dstOff = buf ? SA0_OFF : SA1_OFF;
#pragma unroll
            for (int c = 0; c < 8; c++)
                if (c < kc2)
                    cp_async16(sb + dstOff + tid * RP_A + c * 16, src + tid * 128 + c * 16);
            CP_COMMIT();
        }

        uint32_t aTile = sb + (buf ? SA1_OFF : SA0_OFF);
#pragma unroll 1
        for (int mb = 0; mb < 8; mb++) {
            uint32_t aBase = aTile + (aRowBase + mb * 16) * RP_A + aCol;
            float acc[8][4];
#pragma unroll
            for (int t = 0; t < 8; t++)
#pragma unroll
                for (int q = 0; q < 4; q++) acc[t][q] = 0.f;

#pragma unroll
            for (int ks = 0; ks < 4; ks++) {
                if (ks < kmax) {
                    uint32_t Ah[4];
                    ldsm_x4(aBase + ks * 32, Ah[0], Ah[1], Ah[2], Ah[3]);
#pragma unroll
                    for (int nt = 0; nt < 8; nt++)
                        mma16816(acc[nt], Ah, Bh[ks][nt * 2], Bh[ks][nt * 2 + 1]);
                }
            }

            float p0 = 0.f, p1 = 0.f;
#pragma unroll
            for (int nt = 0; nt < 8; nt++) {
                int col = nc * 64 + nt * 8 + cq;
                float b1a = sB1[col], b1b = sB1[col + 1];
                float w3a = sW3[col], w3b = sW3[col + 1];
                p0 = fmaf(fmaxf(acc[nt][0] + b1a, 0.f), w3a, p0);
                p0 = fmaf(fmaxf(acc[nt][1] + b1b, 0.f), w3b, p0);
                p1 = fmaf(fmaxf(acc[nt][2] + b1a, 0.f), w3a, p1);
                p1 = fmaf(fmaxf(acc[nt][3] + b1b, 0.f), w3b, p1);
            }
#pragma unroll
            for (int off = 1; off <= 2; off <<= 1) {
                p0 += __shfl_xor_sync(0xFFFFFFFFu, p0, off);
                p1 += __shfl_xor_sync(0xFFFFFFFFu, p1, off);
            }
            if ((lane & 3) == 0) {
                int row = rh * 128 + mb * 16 + rq;
                psum[buf * 1024 + row * 4 + nc] = p0;
                psum[buf * 1024 + (row + 8) * 4 + nc] = p1;
            }
        }
        __syncthreads();
        {
            float o = psum[buf * 1024 + tid * 4 + 0] + psum[buf * 1024 + tid * 4 + 1] +
                      psum[buf * 1024 + tid * 4 + 2] + psum[buf * 1024 + tid * 4 + 3] + b3v;
            size_t grow = (size_t)(tile0 + j) * 256 + tid;
            outX[grow * 64 + i] = o;
            outYr[grow * 128 + i] = o;
        }
    }
}

// ---------------------------------------------------------------------------
extern "C" void kernel_launch(void* const* d_in, const int* in_sizes, int n_in,
                              void* d_out, int out_size) {
    const float* x      = (const float*)d_in[0];
    const float* eps    = (const float*)d_in[1];
    const float* enc1_w = (const float*)d_in[2];
    const float* enc1_b = (const float*)d_in[3];
    const float* enc3_w = (const float*)d_in[4];
    const float* enc3_b = (const float*)d_in[5];
    const float* dec1_w = (const float*)d_in[6];
    const float* dec1_b = (const float*)d_in[7];
    const float* dec3_w = (const float*)d_in[8];
    const float* dec3_b = (const float*)d_in[9];
    const unsigned char* bmask = (const unsigned char*)d_in[10];
    (void)n_in; (void)in_sizes; (void)out_size;

    float* out   = (float*)d_out;
    float* outX  = out;
    float* outMu = out + (size_t)BATCH * DD;
    float* outLv = out + (size_t)2 * BATCH * DD;
    float* outYr = out + (size_t)3 * BATCH * DD;

    size_t sEnc = 176640;
    size_t sDec = 83968;
    cudaFuncSetAttribute(enc_mma_kernel, cudaFuncAttributeMaxDynamicSharedMemorySize, (int)sEnc);
    cudaFuncSetAttribute(dec_mma_kernel, cudaFuncAttributeMaxDynamicSharedMemorySize, (int)sDec);

    mask_expand_kernel<<<1, 256>>>(bmask);
    wprep_kernel<<<DD, 256>>>(dec1_w);
    ewprep_kernel<<<32, 256>>>(enc1_w, enc3_w);
    xprep_kernel<<<(BATCH * 32) / 256, 256>>>((const float2*)x);
    zero_yr_kernel<<<(BATCH * 16) / 256, 256>>>((float4*)outYr);
    enc_mma_kernel<<<BATCH / 256, 256, sEnc>>>(eps, enc1_b, enc3_b, outMu, outLv);
    dec_mma_kernel<<<dim3(DD, NT256 / 16), 256, sDec>>>(dec1_b, dec3_w, dec3_b, outX, outYr);
}

// round 14
// speedup vs baseline: 2.7604x; 1.0272x over previous
#include <cuda_runtime.h>
#include <cuda_fp16.h>
#include <cstdint>

// ---------------------------------------------------------------------------
// CausalVAE2: B=262144, D=64, HID=256
// out layout: [x_out B*64][mu B*64][log_var B*64][y_recon B*128]
// Encoder + decoder on mma.sync fp16 (1-term). Decoder epilogue MMA-ized:
// relu(H)+b1 -> fp16 A-fragments -> dot(w3) via 4 chained MMAs (C layout ==
// A layout). zero_yr folded into decoder store.
// ---------------------------------------------------------------------------

#define BATCH 262144
#define DD 64
#define HID 256
#define NT256 (BATCH / 256)           // 1024 row tiles of 256

// Scratch (device globals)
__device__ __align__(16) unsigned char g_abf[(size_t)BATCH * 128];  // 32MB eps_y fp16 [row][64k]
__device__ __align__(16) unsigned char g_xf16[(size_t)BATCH * 128]; // 32MB x fp16 [row][64k]
__device__ __align__(16) unsigned char g_wbf[(size_t)DD * 32768];   // 2MB dec W' [n][k] fp16
__device__ __align__(16) unsigned char g_ew1[256 * 128];            // enc W1 B-layout fp16
__device__ __align__(16) unsigned char g_ew2[128 * 512];            // enc W2 B-layout fp16
__device__ int g_mask[DD * DD];

// ---- baseline tensor-core primitives --------------------------------------
static __device__ __forceinline__ uint32_t smem_u32(const void* p) {
    uint32_t a;
    asm("{ .reg .u64 t; cvta.to.shared.u64 t, %1; cvt.u32.u64 %0, t; }" : "=r"(a) : "l"(p));
    return a;
}
static __device__ __forceinline__ void ldsm_x4(uint32_t addr, uint32_t& r0, uint32_t& r1,
                                               uint32_t& r2, uint32_t& r3) {
    asm volatile("ldmatrix.sync.aligned.m8n8.x4.shared.b16 {%0,%1,%2,%3}, [%4];"
                 : "=r"(r0), "=r"(r1), "=r"(r2), "=r"(r3) : "r"(addr));
}
static __device__ __forceinline__ void mma16816(float* d, const uint32_t* a,
                                                uint32_t b0, uint32_t b1) {
    asm volatile("mma.sync.aligned.m16n8k16.row.col.f32.f16.f16.f32 "
                 "{%0,%1,%2,%3}, {%4,%5,%6,%7}, {%8,%9}, {%0,%1,%2,%3};"
                 : "+f"(d[0]), "+f"(d[1]), "+f"(d[2]), "+f"(d[3])
                 : "r"(a[0]), "r"(a[1]), "r"(a[2]), "r"(a[3]), "r"(b0), "r"(b1));
}
static __device__ __forceinline__ void cp_async16(uint32_t dst, const void* src) {
    asm volatile("cp.async.cg.shared.global [%0], [%1], 16;" :: "r"(dst), "l"(src));
}
#define CP_COMMIT() asm volatile("cp.async.commit_group;" ::: "memory")
#define CP_WAIT0()  asm volatile("cp.async.wait_group 0;" ::: "memory")

extern __shared__ __align__(1024) char smemraw[];

// ---------------------------------------------------------------------------
// Mask decode (robust to bool delivered as u8 / i32 / f32)
// ---------------------------------------------------------------------------
__global__ void mask_expand_kernel(const unsigned char* __restrict__ mb) {
    __shared__ int flags[2];
    __shared__ int s_mode;
    int tid = threadIdx.x;
    if (tid < 2) flags[tid] = 0;
    __syncthreads();
    for (int idx = tid; idx < DD * DD; idx += blockDim.x) {
        unsigned char b = mb[idx];
        if ((idx & 3) != 0 && b != 0) {
            atomicOr(&flags[1], 1);
            if (b > 1) atomicOr(&flags[0], 1);
        }
    }
    __syncthreads();
    if (tid == 0) s_mode = flags[0] ? 2 : (flags[1] ? 1 : 0);
    __syncthreads();
    int mode = s_mode;
    for (int idx = tid; idx < DD * DD; idx += blockDim.x) {
        int v;
        if (mode == 2)      v = (((const float*)mb)[idx] != 0.0f);
        else if (mode == 1) v = (mb[idx] != 0);
        else                v = (((const int*)mb)[idx] != 0);
        g_mask[idx] = v;
    }
}

// ---------------------------------------------------------------------------
// Decoder W-prep: masked dec1_w -> fp16, layout [n][k].
// ---------------------------------------------------------------------------
__global__ void wprep_kernel(const float* __restrict__ w1g) {
    int i = blockIdx.x, tid = threadIdx.x;
    unsigned char* wb = g_wbf + (size_t)i * 32768;
    for (int idx = tid; idx < DD * HID; idx += blockDim.x) {
        int k = idx >> 8, n = idx & 255;
        float m = (float)g_mask[k * DD + i];
        float w = w1g[(size_t)i * DD * HID + (size_t)k * HID + n] * m;
        *(__half*)(wb + n * 128 + k * 2) = __float2half_rn(w);
    }
}

// ---------------------------------------------------------------------------
// Encoder W-prep: enc1_w -> [n][k]; enc3_w -> [n][k]. fp16.
// ---------------------------------------------------------------------------
__global__ void ewprep_kernel(const float* __restrict__ w1,
                              const float* __restrict__ w2) {
    int t = blockIdx.x * 256 + threadIdx.x;
    int stride = gridDim.x * 256;
    for (int idx = t; idx < 64 * 256; idx += stride) {
        int n = idx >> 6, k = idx & 63;
        *(__half*)(g_ew1 + n * 128 + k * 2) = __float2half_rn(w1[k * 256 + n]);
    }
    for (int idx = t; idx < 256 * 128; idx += stride) {
        int n = idx >> 8, k = idx & 255;
        *(__half*)(g_ew2 + n * 512 + k * 2) = __float2half_rn(w2[k * 128 + n]);
    }
}

// ---------------------------------------------------------------------------
// x fp32 -> fp16 rows [row][64k]
// ---------------------------------------------------------------------------
__global__ void xprep_kernel(const float2* __restrict__ x) {
    size_t idx = (size_t)blockIdx.x * blockDim.x + threadIdx.x;
    float2 v = x[idx];
    ((__half2*)g_xf16)[idx] = __floats2half2_rn(v.x, v.y);
}

// ---------------------------------------------------------------------------
// Tensor-core fused encoder (R13, unchanged).
// ---------------------------------------------------------------------------
#define E_SB1 0
#define E_SB2 1024
#define E_SW1 1536
#define E_SW2 38400
#define E_SX  105984
#define E_SH  142848

__global__ __launch_bounds__(256, 1)
void enc_mma_kernel(const float* __restrict__ eps,
                    const float* __restrict__ b1g,
                    const float* __restrict__ b2g,
                    float* __restrict__ outMu,
                    float* __restrict__ outLv) {
    uint32_t sb = smem_u32(smemraw);
    float* sB1e = (float*)(smemraw + E_SB1);
    float* sB2e = (float*)(smemraw + E_SB2);
    int tid = threadIdx.x, wid = tid >> 5, lane = tid & 31;
    int row0 = blockIdx.x * 256;
    int r8 = lane & 7, g = lane >> 3;
    int mt = wid & 3, nh = wid >> 2;
    int cq = (lane & 3) * 2, rq = lane >> 2;

    sB1e[tid] = b1g[tid];
    if (tid < 128) sB2e[tid] = b2g[tid];
#pragma unroll
    for (int c = 0; c < 8; c++)
        cp_async16(sb + E_SW1 + tid * 144 + c * 16, g_ew1 + tid * 128 + c * 16);
#pragma unroll
    for (int c = 0; c < 16; c++)
        cp_async16(sb + E_SW2 + (tid >> 1) * 528 + (tid & 1) * 256 + c * 16,
                   g_ew2 + (tid >> 1) * 512 + (tid & 1) * 256 + c * 16);
#pragma unroll
    for (int c = 0; c < 8; c++)
        cp_async16(sb + E_SX + tid * 144 + c * 16,
                   g_xf16 + (size_t)(row0 + tid) * 128 + c * 16);
    CP_COMMIT();
    CP_WAIT0();
    __syncthreads();

    for (int sbk = 0; sbk < 4; sbk++) {
        if (sbk) __syncthreads();

        float acc1[16][4];
#pragma unroll
        for (int t = 0; t < 16; t++)
#pragma unroll
            for (int q = 0; q < 4; q++) acc1[t][q] = 0.f;
        {
            uint32_t aBase = sb + E_SX + (uint32_t)(sbk * 64 + mt * 16 + (g & 1) * 8 + r8) * 144
                             + (uint32_t)((g >> 1) * 16);
            uint32_t bBase = sb + E_SW1 + (uint32_t)(nh * 128 + (g >> 1) * 8 + r8) * 144
                             + (uint32_t)((g & 1) * 16);
#pragma unroll
            for (int ks = 0; ks < 4; ks++) {
                uint32_t Ah[4];
                ldsm_x4(aBase + ks * 32, Ah[0], Ah[1], Ah[2], Ah[3]);
#pragma unroll
                for (int tp = 0; tp < 8; tp++) {
                    uint32_t Bq[4];
                    ldsm_x4(bBase + tp * 16 * 144 + ks * 32, Bq[0], Bq[1], Bq[2], Bq[3]);
                    mma16816(acc1[tp * 2], Ah, Bq[0], Bq[1]);
                    mma16816(acc1[tp * 2 + 1], Ah, Bq[2], Bq[3]);
                }
            }
        }
#pragma unroll
        for (int nt = 0; nt < 16; nt++) {
            int col = nh * 128 + nt * 8 + cq;
            float b1a = sB1e[col], b1b = sB1e[col + 1];
            int row = mt * 16 + rq;
            __half2 h01 = __floats2half2_rn(fmaxf(acc1[nt][0] + b1a, 0.f),
                                            fmaxf(acc1[nt][1] + b1b, 0.f));
            __half2 h23 = __floats2half2_rn(fmaxf(acc1[nt][2] + b1a, 0.f),
                                            fmaxf(acc1[nt][3] + b1b, 0.f));
            *(__half2*)(smemraw + E_SH + row * 528 + col * 2) = h01;
            *(__half2*)(smemraw + E_SH + (row + 8) * 528 + col * 2) = h23;
        }
        __syncthreads();

        float acc2[8][4];
#pragma unroll
        for (int t = 0; t < 8; t++)
#pragma unroll
            for (int q = 0; q < 4; q++) acc2[t][q] = 0.f;
        {
            uint32_t aBase = sb + E_SH + (uint32_t)(mt * 16 + (g & 1) * 8 + r8) * 528
                             + (uint32_t)((g >> 1) * 16);
            uint32_t bBase = sb + E_SW2 + (uint32_t)(nh * 64 + (g >> 1) * 8 + r8) * 528
                             + (uint32_t)((g & 1) * 16);
#pragma unroll
            for (int ks = 0; ks < 16; ks++) {
                uint32_t Ah[4];
                ldsm_x4(aBase + ks * 32, Ah[0], Ah[1], Ah[2], Ah[3]);
#pragma unroll
                for (int tp = 0; tp < 4; tp++) {
                    uint32_t Bq[4];
                    ldsm_x4(bBase + tp * 16 * 528 + ks * 32, Bq[0], Bq[1], Bq[2], Bq[3]);
                    mma16816(acc2[tp * 2], Ah, Bq[0], Bq[1]);
                    mma16816(acc2[tp * 2 + 1], Ah, Bq[2], Bq[3]);
                }
            }
        }
        __syncthreads();
#pragma unroll
        for (int nt = 0; nt < 8; nt++) {
            int col = nh * 64 + nt * 8 + cq;
            float b2a = sB2e[col], b2b = sB2e[col + 1];
            int row = mt * 16 + rq;
            *(float2*)(smemraw + E_SH + row * 528 + col * 4) =
                make_float2(acc2[nt][0] + b2a, acc2[nt][1] + b2b);
            *(float2*)(smemraw + E_SH + (row + 8) * 528 + col * 4) =
                make_float2(acc2[nt][2] + b2a, acc2[nt][3] + b2b);
        }
        __syncthreads();

        for (int idx = tid; idx < 64 * 64; idx += 256) {
            int r = idx >> 6, c = idx & 63;
            size_t rowAbs = (size_t)row0 + sbk * 64 + r;
            float mu = *(const float*)(smemraw + E_SH + r * 528 + c * 4);
            float lv = *(const float*)(smemraw + E_SH + r * 528 + (64 + c) * 4);
            float e = eps[rowAbs * DD + c];
            float ey = mu + expf(lv * 0.5f) * e;
            outMu[rowAbs * DD + c] = mu;
            outLv[rowAbs * DD + c] = lv;
            *(__half*)(g_abf + rowAbs * 128 + c * 2) = __float2half_rn(ey);
        }
    }
}

// ---------------------------------------------------------------------------
// Decoder v6: fp16 1-term, register-resident B, K truncation, M=256 tiles,
// 2 CTAs/SM, MMA-ized epilogue (relu(H)+b1 in f16x2 -> dot(w3) via 4 MMAs),
// zero_yr folded into store.
// smem: sB1h (half2[128]) @0, psum[2][256][4] @2048,
//       A0 @10240 (256x144), A1 @47104; W' staged transiently at @10240.
// Total 83968 B -> 2 CTAs/SM.
// ---------------------------------------------------------------------------
#define RP_A  144
#define RP_W  144
#define SW_OFF  10240
#define SA0_OFF 10240
#define SA1_OFF 47104
#define PSUM_OFF 2048

__global__ __launch_bounds__(256, 2)
void dec_mma_kernel(const float* __restrict__ b1g,
                    const float* __restrict__ w3g,
                    const float* __restrict__ b3g,
                    float* __restrict__ outX,
                    float* __restrict__ outYr) {
    uint32_t sb = smem_u32(smemraw);
    __half2* sB1h = (__half2*)smemraw;            // 128 half2 (512 B)
    float* psum = (float*)(smemraw + PSUM_OFF);   // [2][256][4]
    int tid = threadIdx.x, wid = tid >> 5, lane = tid & 31;
    int i = blockIdx.x;
    int tile0 = blockIdx.y * 16;
    int nc = wid & 3, rh = wid >> 2;
    const int kmax = (i >> 4) + 1;
    const int kc2 = 2 * kmax;

    // ---- stage W' fp16 + packed b1 ----
    {
        const unsigned char* src = g_wbf + (size_t)i * 32768;
#pragma unroll
        for (int c = 0; c < 8; c++)
            if (c < kc2)
                cp_async16(sb + SW_OFF + tid * RP_W + c * 16, src + tid * 128 + c * 16);
        CP_COMMIT();
        if (tid < 128)
            sB1h[tid] = __floats2half2_rn(b1g[i * HID + 2 * tid], b1g[i * HID + 2 * tid + 1]);
    }
    float b3v = b3g[i];

    // ---- build this warp's w3 B-fragments (col 0 = w3, cols 1..7 = 0) ----
    uint32_t w3f[4][2];
#pragma unroll
    for (int ks2 = 0; ks2 < 4; ks2++) { w3f[ks2][0] = 0u; w3f[ks2][1] = 0u; }
    if ((lane >> 2) == 0) {
#pragma unroll
        for (int ks2 = 0; ks2 < 4; ks2++) {
            int k0 = nc * 64 + ks2 * 16 + (lane & 3) * 2;
            __half2 lo = __floats2half2_rn(w3g[i * HID + k0], w3g[i * HID + k0 + 1]);
            __half2 hi = __floats2half2_rn(w3g[i * HID + k0 + 8], w3g[i * HID + k0 + 9]);
            w3f[ks2][0] = *(uint32_t*)&lo;
            w3f[ks2][1] = *(uint32_t*)&hi;
        }
    }
    CP_WAIT0();
    __syncthreads();

    // ---- load this warp's main-GEMM B fragments into registers ----
    int r8 = lane & 7, g = lane >> 3;
    uint32_t Bh[4][16];
#pragma unroll
    for (int ks = 0; ks < 4; ks++)
#pragma unroll
        for (int q = 0; q < 16; q++) Bh[ks][q] = 0u;
    {
        uint32_t bRow = (uint32_t)((g >> 1) * 8 + r8);
        uint32_t bCol = (uint32_t)((g & 1) * 16);
        uint32_t bBase = sb + SW_OFF + (uint32_t)(nc * 64 + bRow) * RP_W + bCol;
#pragma unroll
        for (int ks = 0; ks < 4; ks++) {
            if (ks < kmax) {
#pragma unroll
                for (int tp = 0; tp < 4; tp++) {
                    uint32_t a = bBase + tp * 16 * RP_W + ks * 32;
                    ldsm_x4(a, Bh[ks][tp * 4], Bh[ks][tp * 4 + 1],
                            Bh[ks][tp * 4 + 2], Bh[ks][tp * 4 + 3]);
                }
            }
        }
    }
    __syncthreads();   // W' region free; A buffers may reuse it

    // ---- prefetch A tile 0 ----
    {
        const unsigned char* src = g_abf + (size_t)tile0 * 256 * 128;
#pragma unroll
        for (int c = 0; c < 8; c++)
            if (c < kc2)
                cp_async16(sb + SA0_OFF + tid * RP_A + c * 16, src + tid * 128 + c * 16);
        CP_COMMIT();
    }

    uint32_t aRowBase = (uint32_t)(rh * 128 + (g & 1) * 8 + r8);
    uint32_t aCol = (uint32_t)((g >> 1) * 16);
    int rq = lane >> 2;
    uint32_t b1addr = sb + (uint32_t)((lane & 3) * 4);   // + nt*16 per step

    for (int j = 0; j < 16; j++) {
        CP_WAIT0();
        __syncthreads();
        int buf = j & 1;
        if (j + 1 < 16) {
            const unsigned char* src = g_abf + (size_t)(tile0 + j + 1) * 256 * 128;
            uint32_t dstOff = buf ? SA0_OFF : SA1_OFF;
#pragma unroll
            for (int c = 0; c < 8; c++)
                if (c < kc2)
                    cp_async16(sb + dstOff + tid * RP_A + c * 16, src + tid * 128 + c * 16);
            CP_COMMIT();
        }

        uint32_t aTile = sb + (buf ? SA1_OFF : SA0_OFF);
#pragma unroll 1
        for (int mb = 0; mb < 8; mb++) {
            uint32_t aBase = aTile + (aRowBase + mb * 16) * RP_A + aCol;
            float acc[8][4];
#pragma unroll
            for (int t = 0; t < 8; t++)
#pragma unroll
                for (int q = 0; q < 4; q++) acc[t][q] = 0.f;

#pragma unroll
            for (int ks = 0; ks < 4; ks++) {
                if (ks < kmax) {
                    uint32_t Ah[4];
                    ldsm_x4(aBase + ks * 32, Ah[0], Ah[1], Ah[2], Ah[3]);
#pragma unroll
                    for (int nt = 0; nt < 8; nt++)
                        mma16816(acc[nt], Ah, Bh[ks][nt * 2], Bh[ks][nt * 2 + 1]);
                }
            }

            // ---- MMA-ized epilogue: relu(acc+b1) fp16 -> dot(w3) via 4 MMAs
            uint32_t h2[16];
#pragma unroll
            for (int nt = 0; nt < 8; nt++) {
                uint32_t b1p;
                asm("ld.shared.b32 %0, [%1];" : "=r"(b1p)
                    : "r"(b1addr + (uint32_t)(nc * 128 + nt * 16)));
                uint32_t p0, p1;
                asm("cvt.rn.f16x2.f32 %0, %1, %2;" : "=r"(p0)
                    : "f"(acc[nt][1]), "f"(acc[nt][0]));
                asm("cvt.rn.f16x2.f32 %0, %1, %2;" : "=r"(p1)
                    : "f"(acc[nt][3]), "f"(acc[nt][2]));
                asm("add.rn.f16x2 %0, %0, %1;" : "+r"(p0) : "r"(b1p));
                asm("add.rn.f16x2 %0, %0, %1;" : "+r"(p1) : "r"(b1p));
                asm("max.f16x2 %0, %0, %1;" : "+r"(p0) : "r"(0u));
                asm("max.f16x2 %0, %0, %1;" : "+r"(p1) : "r"(0u));
                h2[nt * 2] = p0;
                h2[nt * 2 + 1] = p1;
            }
            float dacc[4] = {0.f, 0.f, 0.f, 0.f};
#pragma unroll
            for (int ks2 = 0; ks2 < 4; ks2++) {
                uint32_t Af[4] = {h2[4 * ks2], h2[4 * ks2 + 1],
                                  h2[4 * ks2 + 2], h2[4 * ks2 + 3]};
                mma16816(dacc, Af, w3f[ks2][0], w3f[ks2][1]);
            }
            if ((lane & 3) == 0) {
                int row = rh * 128 + mb * 16 + rq;
                psum[buf * 1024 + row * 4 + nc] = dacc[0];
                psum[buf * 1024 + (row + 8) * 4 + nc] = dacc[2];
            }
        }
        __syncthreads();
        {
            float o = psum[buf * 1024 + tid * 4 + 0] + psum[buf * 1024 + tid * 4 + 1] +
                      psum[buf * 1024 + tid * 4 + 2] + psum[buf * 1024 + tid * 4 + 3] + b3v;
            size_t grow = (size_t)(tile0 + j) * 256 + tid;
            outX[grow * 64 + i] = o;
            outYr[grow * 128 + i] = o;
            outYr[grow * 128 + 64 + i] = 0.f;   // zero half folded in (col 64+i)
        }
    }
}

// ---------------------------------------------------------------------------
extern "C" void kernel_launch(void* const* d_in, const int* in_sizes, int n_in,
                              void* d_out, int out_size) {
    const float* x      = (const float*)d_in[0];
    const float* eps    = (const float*)d_in[1];
    const float* enc1_w = (const float*)d_in[2];
    const float* enc1_b = (const float*)d_in[3];
    const float* enc3_w = (const float*)d_in[4];
    const float* enc3_b = (const float*)d_in[5];
    const float* dec1_w = (const float*)d_in[6];
    const float* dec1_b = (const float*)d_in[7];
    const float* dec3_w = (const float*)d_in[8];
    const float* dec3_b = (const float*)d_in[9];
    const unsigned char* bmask = (const unsigned char*)d_in[10];
    (void)n_in; (void)in_sizes; (void)out_size;

    float* out   = (float*)d_out;
    float* outX  = out;
    float* outMu = out + (size_t)BATCH * DD;
    float* outLv = out + (size_t)2 * BATCH * DD;
    float* outYr = out + (size_t)3 * BATCH * DD;

    size_t sEnc = 176640;
    size_t sDec = 83968;
    cudaFuncSetAttribute(enc_mma_kernel, cudaFuncAttributeMaxDynamicSharedMemorySize, (int)sEnc);
    cudaFuncSetAttribute(dec_mma_kernel, cudaFuncAttributeMaxDynamicSharedMemorySize, (int)sDec);

    mask_expand_kernel<<<1, 256>>>(bmask);
    wprep_kernel<<<DD, 256>>>(dec1_w);
    ewprep_kernel<<<32, 256>>>(enc1_w, enc3_w);
    xprep_kernel<<<(BATCH * 32) / 256, 256>>>((const float2*)x);
    enc_mma_kernel<<<BATCH / 256, 256, sEnc>>>(eps, enc1_b, enc3_b, outMu, outLv);
    dec_mma_kernel<<<dim3(DD, NT256 / 16), 256, sDec>>>(dec1_b, dec3_w, dec3_b, outX, outYr);
}